// round 6
// baseline (speedup 1.0000x reference)
#include <cuda_runtime.h>
#include <cuda_bf16.h>
#include <math.h>
#include <stdint.h>

#define M_TOTAL 131072  // 2048 windows * 64 tokens

// ---------------- scratch (device globals) ----------------
__device__ float         g_qkv[(size_t)M_TOTAL * 768];   // fp32 qkv (qn|kn|v), q/k pre-normalized
__device__ __nv_bfloat16 g_a2[(size_t)M_TOTAL * 512];    // attn-out split [hi|lo]
__device__ __nv_bfloat16 g_wq[768 * 768];                // qkv_w split [hi|hi|lo]
__device__ __nv_bfloat16 g_wp[256 * 768];                // proj_w split [hi|hi|lo]
__device__ float         g_bias16[8 * 64 * 64];          // 16*sigmoid(rpb)
__device__ float         g_qkvbias[768];                 // [q_bias | 0 | v_bias]

// ---------------- PTX helpers (baseline ISA only) ----------------
__device__ __forceinline__ uint32_t smem_u32(const void* p) {
    uint32_t a;
    asm("{ .reg .u64 t; cvta.to.shared.u64 t, %1; cvt.u32.u64 %0, t; }" : "=r"(a) : "l"(p));
    return a;
}

#define CP_ASYNC16(dst, src) \
    asm volatile("cp.async.cg.shared.global [%0], [%1], 16;" :: "r"((uint32_t)(dst)), "l"(src))
#define CP_COMMIT() asm volatile("cp.async.commit_group;" ::: "memory")
#define CP_WAIT(n)  asm volatile("cp.async.wait_group %0;" :: "n"(n) : "memory")

#define LDSM_X4(r, addr) \
    asm volatile("ldmatrix.sync.aligned.m8n8.x4.shared.b16 {%0,%1,%2,%3}, [%4];" \
                 : "=r"((r)[0]), "=r"((r)[1]), "=r"((r)[2]), "=r"((r)[3]) : "r"(addr))

#define MMA16816(c, a, b0, b1) \
    asm volatile("mma.sync.aligned.m16n8k16.row.col.f32.bf16.bf16.f32 " \
                 "{%0,%1,%2,%3}, {%4,%5,%6,%7}, {%8,%9}, {%0,%1,%2,%3};" \
                 : "+f"((c)[0]), "+f"((c)[1]), "+f"((c)[2]), "+f"((c)[3]) \
                 : "r"((a)[0]), "r"((a)[1]), "r"((a)[2]), "r"((a)[3]), "r"(b0), "r"(b1))

__device__ __forceinline__ void split2(float v, unsigned short& h, unsigned short& l) {
    __nv_bfloat16 hb = __float2bfloat16_rn(v);
    float r = v - __bfloat162float(hb);
    __nv_bfloat16 lb = __float2bfloat16_rn(r);
    h = *(unsigned short*)&hb;
    l = *(unsigned short*)&lb;
}
__device__ __forceinline__ unsigned short bfhi(float v) {
    __nv_bfloat16 hb = __float2bfloat16_rn(v);
    return *(unsigned short*)&hb;
}

// ---------------- prep: CPB MLP bias + qkv bias vector ----------------
__global__ void prep_kernel(const float* __restrict__ cpb_w1,
                            const float* __restrict__ cpb_b1,
                            const float* __restrict__ cpb_w2,
                            const float* __restrict__ q_bias,
                            const float* __restrict__ v_bias) {
    __shared__ float bt[225][8];
    const int t = threadIdx.x;
    for (int i = t; i < 768; i += 256)
        g_qkvbias[i] = (i < 256) ? q_bias[i] : ((i < 512) ? 0.0f : v_bias[i - 512]);
    if (t < 225) {
        int i = t / 15, j = t % 15;
        float t0 = (float)(i - 7) * (8.0f / 7.0f);
        float t1 = (float)(j - 7) * (8.0f / 7.0f);
        t0 = copysignf(log2f(fabsf(t0) + 1.0f), t0) * (1.0f / 3.0f);
        t1 = copysignf(log2f(fabsf(t1) + 1.0f), t1) * (1.0f / 3.0f);
        float acc[8];
#pragma unroll
        for (int hh = 0; hh < 8; hh++) acc[hh] = 0.0f;
        for (int u = 0; u < 512; u++) {
            float hu = fmaxf(cpb_w1[2 * u] * t0 + cpb_w1[2 * u + 1] * t1 + cpb_b1[u], 0.0f);
#pragma unroll
            for (int hh = 0; hh < 8; hh++) acc[hh] += cpb_w2[hh * 512 + u] * hu;
        }
#pragma unroll
        for (int hh = 0; hh < 8; hh++) bt[t][hh] = acc[hh];
    }
    __syncthreads();
    for (int idx = t; idx < 8 * 64 * 64; idx += 256) {
        int hh = idx >> 12, n = (idx >> 6) & 63, m = idx & 63;
        int rid = ((n >> 3) - (m >> 3) + 7) * 15 + ((n & 7) - (m & 7) + 7);
        g_bias16[idx] = 16.0f / (1.0f + __expf(-bt[rid][hh]));
    }
}

// ---------------- split weights -> [hi|hi|lo] ----------------
template <int WHICH>
__global__ __launch_bounds__(256) void split_w(const float* __restrict__ w) {
    __nv_bfloat16* dst = (WHICH == 0) ? g_wq : g_wp;
    size_t u = ((size_t)blockIdx.x * 256 + threadIdx.x) * 4;
    size_t row = u >> 8;
    int col = (int)(u & 255);
    float4 v = *(const float4*)(w + u);
    unsigned short h[4], l[4];
    split2(v.x, h[0], l[0]); split2(v.y, h[1], l[1]);
    split2(v.z, h[2], l[2]); split2(v.w, h[3], l[3]);
    uint2 hv, lv;
    hv.x = (uint32_t)h[0] | ((uint32_t)h[1] << 16);
    hv.y = (uint32_t)h[2] | ((uint32_t)h[3] << 16);
    lv.x = (uint32_t)l[0] | ((uint32_t)l[1] << 16);
    lv.y = (uint32_t)l[2] | ((uint32_t)l[3] << 16);
    __nv_bfloat16* d = dst + row * 768 + col;
    *(uint2*)d = hv;
    *(uint2*)(d + 256) = hv;
    *(uint2*)(d + 512) = lv;
}

// ---------------- qkv GEMM: fused fp32->bf16-split A loader + normalize epilogue --
// C[M,768] = split(x)[M,768'] @ g_wq[768,768']^T + bias; q/k rows normalized (q*scale).
// 3-stage pipeline; stage = A 16KB + W 16KB.
__global__ __launch_bounds__(256) void qkv_gemm(const float* __restrict__ x,
                                                const float* __restrict__ ls) {
    extern __shared__ __align__(128) char smem[];
    const uint32_t sbase = smem_u32(smem);
    const int t = threadIdx.x;
    const int lane = t & 31, wid = t >> 5;
    const int bn = blockIdx.x * 128;
    const size_t bm = (size_t)blockIdx.y * 128;
    const int wm = (wid >> 2) * 64;
    const int wn = (wid & 3) * 32;

    const __nv_bfloat16* Wg = g_wq + (size_t)bn * 768;

    auto loadW = [&](int c, int s) {
        uint32_t bb = sbase + s * 32768 + 16384;
        const char* Bp = (const char*)(Wg + c * 64);
#pragma unroll
        for (int i = 0; i < 4; i++) {
            int u = i * 256 + t;
            int row = u >> 3, c16 = u & 7;
            uint32_t off = (uint32_t)(row * 128 + ((c16 ^ (row & 7)) << 4));
            CP_ASYNC16(bb + off, Bp + (size_t)row * 1536 + c16 * 16);
        }
    };

    // A: read fp32 x, split, store selected section to smem (permuted layout)
    auto loadA = [&](int c, int s) {
        char* ab = smem + s * 32768;
        const int sec = c >> 2;  // 0:hi 1:lo 2:hi
        const float* Xp = x + bm * 256 + (c & 3) * 64;
#pragma unroll
        for (int i = 0; i < 4; i++) {
            int u = i * 256 + t;
            int row = u >> 3, c16 = u & 7;
            const float* src = Xp + (size_t)row * 256 + c16 * 8;
            float4 v0 = *(const float4*)src;
            float4 v1 = *(const float4*)(src + 4);
            float f[8] = {v0.x, v0.y, v0.z, v0.w, v1.x, v1.y, v1.z, v1.w};
            unsigned short o[8];
            if (sec == 1) {
#pragma unroll
                for (int q = 0; q < 8; q++) { unsigned short hh, ll; split2(f[q], hh, ll); o[q] = ll; }
            } else {
#pragma unroll
                for (int q = 0; q < 8; q++) o[q] = bfhi(f[q]);
            }
            uint4 pv;
            pv.x = (uint32_t)o[0] | ((uint32_t)o[1] << 16);
            pv.y = (uint32_t)o[2] | ((uint32_t)o[3] << 16);
            pv.z = (uint32_t)o[4] | ((uint32_t)o[5] << 16);
            pv.w = (uint32_t)o[6] | ((uint32_t)o[7] << 16);
            uint32_t off = (uint32_t)(row * 128 + ((c16 ^ (row & 7)) << 4));
            *(uint4*)(ab + off) = pv;
        }
    };

    float acc[4][4][4];
#pragma unroll
    for (int mi = 0; mi < 4; mi++)
#pragma unroll
        for (int ni = 0; ni < 4; ni++)
#pragma unroll
            for (int q = 0; q < 4; q++) acc[mi][ni][q] = 0.0f;

    loadW(0, 0); CP_COMMIT();
    loadW(1, 1); CP_COMMIT();
    loadA(0, 0);
    loadA(1, 1);

    for (int c = 0; c < 12; c++) {
        if (c < 11) CP_WAIT(1); else CP_WAIT(0);
        __syncthreads();
        if (c + 2 < 12) { loadW(c + 2, (c + 2) % 3); CP_COMMIT(); }

        uint32_t ab = sbase + (c % 3) * 32768;
        uint32_t bb = ab + 16384;
#pragma unroll
        for (int ks = 0; ks < 4; ks++) {
            const int kc = ks * 2;
            uint32_t a_regs[4][4];
#pragma unroll
            for (int mi = 0; mi < 4; mi++) {
                int r = wm + mi * 16 + (lane & 15);
                int kk = kc + (lane >> 4);
                LDSM_X4(a_regs[mi], ab + r * 128 + ((kk ^ (r & 7)) << 4));
            }
            uint32_t b_regs[2][4];
#pragma unroll
            for (int np = 0; np < 2; np++) {
                int r = wn + np * 16 + (lane & 15);
                int kk = kc + (lane >> 4);
                LDSM_X4(b_regs[np], bb + r * 128 + ((kk ^ (r & 7)) << 4));
            }
#pragma unroll
            for (int mi = 0; mi < 4; mi++)
#pragma unroll
                for (int ni = 0; ni < 4; ni++) {
                    uint32_t b0 = b_regs[ni >> 1][ni & 1];
                    uint32_t b1 = b_regs[ni >> 1][(ni & 1) + 2];
                    MMA16816(acc[mi][ni], a_regs[mi], b0, b1);
                }
        }
        if (c + 2 < 12) loadA(c + 2, (c + 2) % 3);
    }

    // ---- epilogue: bias, then normalize q (with logit scale) / k per row ----
    const int g = lane >> 2, tt = lane & 3;
    const int cw = bn + wn;             // warp column base = one head's 32 cols
    const bool isq = cw < 256;
    const bool isk = (cw >= 256) && (cw < 512);
    float scale = 1.0f;
    if (isq) scale = __expf(fminf(ls[cw >> 5], 4.6051702f));

#pragma unroll
    for (int mi = 0; mi < 4; mi++) {
        float ss0 = 0.0f, ss1 = 0.0f;
#pragma unroll
        for (int ni = 0; ni < 4; ni++) {
            int col = cw + ni * 8 + tt * 2;
            float b0 = g_qkvbias[col], b1 = g_qkvbias[col + 1];
            acc[mi][ni][0] += b0; acc[mi][ni][1] += b1;
            acc[mi][ni][2] += b0; acc[mi][ni][3] += b1;
            ss0 += acc[mi][ni][0] * acc[mi][ni][0] + acc[mi][ni][1] * acc[mi][ni][1];
            ss1 += acc[mi][ni][2] * acc[mi][ni][2] + acc[mi][ni][3] * acc[mi][ni][3];
        }
        if (isq || isk) {
            ss0 += __shfl_xor_sync(0xffffffffu, ss0, 1);
            ss0 += __shfl_xor_sync(0xffffffffu, ss0, 2);
            ss1 += __shfl_xor_sync(0xffffffffu, ss1, 1);
            ss1 += __shfl_xor_sync(0xffffffffu, ss1, 2);
            float inv0 = scale / fmaxf(sqrtf(ss0), 1e-12f);
            float inv1 = scale / fmaxf(sqrtf(ss1), 1e-12f);
#pragma unroll
            for (int ni = 0; ni < 4; ni++) {
                acc[mi][ni][0] *= inv0; acc[mi][ni][1] *= inv0;
                acc[mi][ni][2] *= inv1; acc[mi][ni][3] *= inv1;
            }
        }
        size_t r0 = bm + wm + mi * 16 + g;
#pragma unroll
        for (int ni = 0; ni < 4; ni++) {
            int col = cw + ni * 8 + tt * 2;
            *(float2*)(g_qkv + r0 * 768 + col) = make_float2(acc[mi][ni][0], acc[mi][ni][1]);
            *(float2*)(g_qkv + (r0 + 8) * 768 + col) = make_float2(acc[mi][ni][2], acc[mi][ni][3]);
        }
    }
}

// ---------------- proj GEMM: A = g_a2 [hi|lo] with section remap ----------------
__global__ __launch_bounds__(256) void proj_gemm(const float* __restrict__ bias,
                                                 float* __restrict__ C) {
    extern __shared__ __align__(128) char smem[];
    const uint32_t sbase = smem_u32(smem);
    const int t = threadIdx.x;
    const int lane = t & 31, wid = t >> 5;
    const int bn = blockIdx.x * 128;
    const size_t bm = (size_t)blockIdx.y * 128;
    const int wm = (wid >> 2) * 64;
    const int wn = (wid & 3) * 32;

    const char* Ab = (const char*)g_a2 + bm * 1024;   // pitch 512 bf16 = 1024B
    const char* Wb = (const char*)(g_wp + (size_t)bn * 768);

    auto load_chunk = [&](int c, int s) {
        uint32_t ab = sbase + s * 32768;
        uint32_t bb = ab + 16384;
        const int sec = c >> 2;
        const int acol0 = (c & 3) * 64 + ((sec == 1) ? 256 : 0);
        const char* Ap = Ab + acol0 * 2;
        const char* Bp = Wb + c * 128;  // 64 bf16 cols = 128B
#pragma unroll
        for (int i = 0; i < 4; i++) {
            int u = i * 256 + t;
            int row = u >> 3, c16 = u & 7;
            uint32_t off = (uint32_t)(row * 128 + ((c16 ^ (row & 7)) << 4));
            CP_ASYNC16(ab + off, Ap + (size_t)row * 1024 + c16 * 16);
            CP_ASYNC16(bb + off, Bp + (size_t)row * 1536 + c16 * 16);
        }
    };

    float acc[4][4][4];
#pragma unroll
    for (int mi = 0; mi < 4; mi++)
#pragma unroll
        for (int ni = 0; ni < 4; ni++)
#pragma unroll
            for (int q = 0; q < 4; q++) acc[mi][ni][q] = 0.0f;

    load_chunk(0, 0);
    CP_COMMIT();

    for (int c = 0; c < 12; c++) {
        if (c + 1 < 12) {
            load_chunk(c + 1, (c + 1) & 1);
            CP_COMMIT();
            CP_WAIT(1);
        } else {
            CP_WAIT(0);
        }
        __syncthreads();
        uint32_t ab = sbase + (c & 1) * 32768;
        uint32_t bb = ab + 16384;
#pragma unroll
        for (int ks = 0; ks < 4; ks++) {
            const int kc = ks * 2;
            uint32_t a_regs[4][4];
#pragma unroll
            for (int mi = 0; mi < 4; mi++) {
                int r = wm + mi * 16 + (lane & 15);
                int kk = kc + (lane >> 4);
                LDSM_X4(a_regs[mi], ab + r * 128 + ((kk ^ (r & 7)) << 4));
            }
            uint32_t b_regs[2][4];
#pragma unroll
            for (int np = 0; np < 2; np++) {
                int r = wn + np * 16 + (lane & 15);
                int kk = kc + (lane >> 4);
                LDSM_X4(b_regs[np], bb + r * 128 + ((kk ^ (r & 7)) << 4));
            }
#pragma unroll
            for (int mi = 0; mi < 4; mi++)
#pragma unroll
                for (int ni = 0; ni < 4; ni++) {
                    uint32_t b0 = b_regs[ni >> 1][ni & 1];
                    uint32_t b1 = b_regs[ni >> 1][(ni & 1) + 2];
                    MMA16816(acc[mi][ni], a_regs[mi], b0, b1);
                }
        }
        __syncthreads();
    }

    const int g = lane >> 2, tt = lane & 3;
#pragma unroll
    for (int mi = 0; mi < 4; mi++) {
        size_t r0 = bm + wm + mi * 16 + g;
#pragma unroll
        for (int ni = 0; ni < 4; ni++) {
            int col = bn + wn + ni * 8 + tt * 2;
            float bv0 = bias[col], bv1 = bias[col + 1];
            float2 v0 = make_float2(acc[mi][ni][0] + bv0, acc[mi][ni][1] + bv1);
            float2 v1 = make_float2(acc[mi][ni][2] + bv0, acc[mi][ni][3] + bv1);
            *(float2*)(C + r0 * 256 + col) = v0;
            *(float2*)(C + (r0 + 8) * 256 + col) = v1;
        }
    }
}

// ---------------- HMMA attention (q/k pre-normalized) ----------------
// smem: Q'[h|l|h] 64x208 @0 ; K'[h|h|l] 64x208 @13312 ; VtH 32x144 @26624 ; VtL @31232
// sO (fp32 64x36) reuses @0 after a syncthreads.
#define ATTN_SMEM 35840
__global__ __launch_bounds__(128) void attn_mma() {
    extern __shared__ __align__(128) char smem[];
    const int b = blockIdx.x, h = blockIdx.y;
    const int t = threadIdx.x;
    const int lane = t & 31, w = t >> 5;
    const uint32_t sb = smem_u32(smem);

    const float* base = g_qkv + (size_t)b * (64 * 768) + h * 32;

    // q,k: coalesced fp32 load -> split -> MMA layouts (q:[h|l|h], k:[h|h|l])
#pragma unroll
    for (int i = 0; i < 4; i++) {
        int idx = t + i * 128;      // 0..511
        int n = idx >> 3;
        int d4 = (idx & 7) << 2;
        const float* rb = base + n * 768 + d4;
        float4 qv = *(const float4*)(rb);
        float4 kv = *(const float4*)(rb + 256);
        unsigned short qh[4], ql[4], kh[4], kl[4];
        split2(qv.x, qh[0], ql[0]); split2(qv.y, qh[1], ql[1]);
        split2(qv.z, qh[2], ql[2]); split2(qv.w, qh[3], ql[3]);
        split2(kv.x, kh[0], kl[0]); split2(kv.y, kh[1], kl[1]);
        split2(kv.z, kh[2], kl[2]); split2(kv.w, kh[3], kl[3]);
        uint2 qhv, qlv, khv, klv;
        qhv.x = (uint32_t)qh[0] | ((uint32_t)qh[1] << 16);
        qhv.y = (uint32_t)qh[2] | ((uint32_t)qh[3] << 16);
        qlv.x = (uint32_t)ql[0] | ((uint32_t)ql[1] << 16);
        qlv.y = (uint32_t)ql[2] | ((uint32_t)ql[3] << 16);
        khv.x = (uint32_t)kh[0] | ((uint32_t)kh[1] << 16);
        khv.y = (uint32_t)kh[2] | ((uint32_t)kh[3] << 16);
        klv.x = (uint32_t)kl[0] | ((uint32_t)kl[1] << 16);
        klv.y = (uint32_t)kl[2] | ((uint32_t)kl[3] << 16);
        char* qd = smem + n * 208 + d4 * 2;
        char* kd = smem + 13312 + n * 208 + d4 * 2;
        *(uint2*)(qd) = qhv; *(uint2*)(qd + 64) = qlv; *(uint2*)(qd + 128) = qhv;
        *(uint2*)(kd) = khv; *(uint2*)(kd + 64) = khv; *(uint2*)(kd + 128) = klv;
    }

    // V: load fp32, split, store transposed Vt[d][m] (hi/lo)
    {
        int m = t >> 1, dh = (t & 1) * 16;
        const float* vr = base + m * 768 + 512 + dh;
        char* vth = smem + 26624;
        char* vtl = smem + 31232;
#pragma unroll
        for (int i = 0; i < 16; i += 4) {
            float4 v4 = *(const float4*)(vr + i);
            float vv[4] = {v4.x, v4.y, v4.z, v4.w};
#pragma unroll
            for (int q = 0; q < 4; q++) {
                unsigned short hh, ll;
                split2(vv[q], hh, ll);
                int d = dh + i + q;
                *(unsigned short*)(vth + d * 144 + m * 2) = hh;
                *(unsigned short*)(vtl + d * 144 + m * 2) = ll;
            }
        }
    }
    __syncthreads();

    // ---- QK^T: S(16x64) per warp, K'=96 ----
    const int R = w * 16;
    const uint32_t qbase = sb;
    const uint32_t kbase = sb + 13312;
    float sacc[8][4];
#pragma unroll
    for (int j = 0; j < 8; j++)
#pragma unroll
        for (int q = 0; q < 4; q++) sacc[j][q] = 0.0f;

#pragma unroll
    for (int kk = 0; kk < 6; kk++) {
        uint32_t a[4];
        {
            int r = R + (lane & 15);
            int ch = 2 * kk + (lane >> 4);
            LDSM_X4(a, qbase + r * 208 + ch * 16);
        }
#pragma unroll
        for (int nt = 0; nt < 4; nt++) {
            uint32_t br[4];
            int r = nt * 16 + (lane & 15);
            int ch = 2 * kk + (lane >> 4);
            LDSM_X4(br, kbase + r * 208 + ch * 16);
            MMA16816(sacc[nt * 2 + 0], a, br[0], br[2]);
            MMA16816(sacc[nt * 2 + 1], a, br[1], br[3]);
        }
    }

    // ---- bias + softmax in C-register layout ----
    const int g = lane >> 2, tt = lane & 3;
    const float* bp = g_bias16 + ((h * 64 + R + g) * 64);
#pragma unroll
    for (int j = 0; j < 8; j++) {
        int col = j * 8 + tt * 2;
        sacc[j][0] += bp[col];
        sacc[j][1] += bp[col + 1];
        sacc[j][2] += bp[col + 512];
        sacc[j][3] += bp[col + 513];
    }
    float m0 = -1e30f, m1 = -1e30f;
#pragma unroll
    for (int j = 0; j < 8; j++) {
        m0 = fmaxf(m0, fmaxf(sacc[j][0], sacc[j][1]));
        m1 = fmaxf(m1, fmaxf(sacc[j][2], sacc[j][3]));
    }
    m0 = fmaxf(m0, __shfl_xor_sync(0xffffffffu, m0, 1));
    m0 = fmaxf(m0, __shfl_xor_sync(0xffffffffu, m0, 2));
    m1 = fmaxf(m1, __shfl_xor_sync(0xffffffffu, m1, 1));
    m1 = fmaxf(m1, __shfl_xor_sync(0xffffffffu, m1, 2));
    float s0 = 0.0f, s1 = 0.0f;
#pragma unroll
    for (int j = 0; j < 8; j++) {
        sacc[j][0] = __expf(sacc[j][0] - m0);
        sacc[j][1] = __expf(sacc[j][1] - m0);
        sacc[j][2] = __expf(sacc[j][2] - m1);
        sacc[j][3] = __expf(sacc[j][3] - m1);
        s0 += sacc[j][0] + sacc[j][1];
        s1 += sacc[j][2] + sacc[j][3];
    }
    s0 += __shfl_xor_sync(0xffffffffu, s0, 1);
    s0 += __shfl_xor_sync(0xffffffffu, s0, 2);
    s1 += __shfl_xor_sync(0xffffffffu, s1, 1);
    s1 += __shfl_xor_sync(0xffffffffu, s1, 2);
    float r0 = 1.0f / s0, r1 = 1.0f / s1;

    // ---- P hi/lo B-fragments from registers ----
    uint32_t bh[8][2], bl[8][2];
#pragma unroll
    for (int j = 0; j < 8; j++) {
        float p0 = sacc[j][0] * r0, p1 = sacc[j][1] * r0;
        float p2 = sacc[j][2] * r1, p3 = sacc[j][3] * r1;
        unsigned short h0, l0, h1, l1, h2, l2, h3, l3;
        split2(p0, h0, l0); split2(p1, h1, l1);
        split2(p2, h2, l2); split2(p3, h3, l3);
        bh[j][0] = (uint32_t)h0 | ((uint32_t)h1 << 16);
        bl[j][0] = (uint32_t)l0 | ((uint32_t)l1 << 16);
        bh[j][1] = (uint32_t)h2 | ((uint32_t)h3 << 16);
        bl[j][1] = (uint32_t)l2 | ((uint32_t)l3 << 16);
    }

    // ---- O^T = V^T P^T: 3 passes ----
    float oacc[2][2][4];
#pragma unroll
    for (int mt = 0; mt < 2; mt++)
#pragma unroll
        for (int nt = 0; nt < 2; nt++)
#pragma unroll
            for (int q = 0; q < 4; q++) oacc[mt][nt][q] = 0.0f;

#pragma unroll
    for (int pass = 0; pass < 3; pass++) {
        const uint32_t vbase = sb + ((pass == 2) ? 31232 : 26624);
        uint32_t (*B)[2] = (pass == 1) ? bl : bh;
#pragma unroll
        for (int mt = 0; mt < 2; mt++) {
#pragma unroll
            for (int s = 0; s < 4; s++) {
                uint32_t a[4];
                int r = mt * 16 + (lane & 15);
                int ch = 2 * s + (lane >> 4);
                LDSM_X4(a, vbase + r * 144 + ch * 16);
                MMA16816(oacc[mt][0], a, B[2 * s][0], B[2 * s + 1][0]);
                MMA16816(oacc[mt][1], a, B[2 * s][1], B[2 * s + 1][1]);
            }
        }
    }

    // ---- stage O (transpose back), then coalesced split write [hi|lo] ----
    __syncthreads();           // all warps done reading Q' region before reuse
    float* sO = (float*)smem;  // 64 x 36 floats
#pragma unroll
    for (int mt = 0; mt < 2; mt++)
#pragma unroll
        for (int nt = 0; nt < 2; nt++) {
            int qr = R + nt * 8 + tt * 2;
            int d = mt * 16 + g;
            sO[qr * 36 + d] = oacc[mt][nt][0];
            sO[(qr + 1) * 36 + d] = oacc[mt][nt][1];
            sO[qr * 36 + d + 8] = oacc[mt][nt][2];
            sO[(qr + 1) * 36 + d + 8] = oacc[mt][nt][3];
        }
    __syncthreads();

    {
        int qr = t >> 1, dh = (t & 1) * 16;
        const float* orow = sO + qr * 36 + dh;
        unsigned short hi[16], lo[16];
#pragma unroll
        for (int i = 0; i < 16; i++) split2(orow[i], hi[i], lo[i]);
        __nv_bfloat16* og = g_a2 + (size_t)(b * 64 + qr) * 512 + h * 32 + dh;
        uint4 hv0, hv1, lv0, lv1;
        hv0.x = (uint32_t)hi[0] | ((uint32_t)hi[1] << 16);
        hv0.y = (uint32_t)hi[2] | ((uint32_t)hi[3] << 16);
        hv0.z = (uint32_t)hi[4] | ((uint32_t)hi[5] << 16);
        hv0.w = (uint32_t)hi[6] | ((uint32_t)hi[7] << 16);
        hv1.x = (uint32_t)hi[8] | ((uint32_t)hi[9] << 16);
        hv1.y = (uint32_t)hi[10] | ((uint32_t)hi[11] << 16);
        hv1.z = (uint32_t)hi[12] | ((uint32_t)hi[13] << 16);
        hv1.w = (uint32_t)hi[14] | ((uint32_t)hi[15] << 16);
        lv0.x = (uint32_t)lo[0] | ((uint32_t)lo[1] << 16);
        lv0.y = (uint32_t)lo[2] | ((uint32_t)lo[3] << 16);
        lv0.z = (uint32_t)lo[4] | ((uint32_t)lo[5] << 16);
        lv0.w = (uint32_t)lo[6] | ((uint32_t)lo[7] << 16);
        lv1.x = (uint32_t)lo[8] | ((uint32_t)lo[9] << 16);
        lv1.y = (uint32_t)lo[10] | ((uint32_t)lo[11] << 16);
        lv1.z = (uint32_t)lo[12] | ((uint32_t)lo[13] << 16);
        lv1.w = (uint32_t)lo[14] | ((uint32_t)lo[15] << 16);
        *(uint4*)(og) = hv0;
        *(uint4*)(og + 8) = hv1;
        *(uint4*)(og + 256) = lv0;
        *(uint4*)(og + 264) = lv1;
    }
}

extern "C" void kernel_launch(void* const* d_in, const int* in_sizes, int n_in,
                              void* d_out, int out_size) {
    const float* x           = (const float*)d_in[0];
    const float* qkv_w       = (const float*)d_in[1];
    const float* q_bias      = (const float*)d_in[2];
    const float* v_bias      = (const float*)d_in[3];
    const float* logit_scale = (const float*)d_in[4];
    const float* cpb_w1      = (const float*)d_in[5];
    const float* cpb_b1      = (const float*)d_in[6];
    const float* cpb_w2      = (const float*)d_in[7];
    const float* proj_w      = (const float*)d_in[8];
    const float* proj_b      = (const float*)d_in[9];
    float* out = (float*)d_out;

    const int QKV_SMEM = 3 * 32768;   // 96 KB
    const int PROJ_SMEM = 2 * 32768;  // 64 KB
    cudaFuncSetAttribute(qkv_gemm, cudaFuncAttributeMaxDynamicSharedMemorySize, QKV_SMEM);
    cudaFuncSetAttribute(proj_gemm, cudaFuncAttributeMaxDynamicSharedMemorySize, PROJ_SMEM);
    cudaFuncSetAttribute(attn_mma, cudaFuncAttributeMaxDynamicSharedMemorySize, ATTN_SMEM);

    prep_kernel<<<1, 256>>>(cpb_w1, cpb_b1, cpb_w2, q_bias, v_bias);
    split_w<0><<<768 * 256 / 4 / 256, 256>>>(qkv_w);
    split_w<1><<<256 * 256 / 4 / 256, 256>>>(proj_w);
    qkv_gemm<<<dim3(6, M_TOTAL / 128), 256, QKV_SMEM>>>(x, logit_scale);
    attn_mma<<<dim3(2048, 8), 128, ATTN_SMEM>>>();
    proj_gemm<<<dim3(2, M_TOTAL / 128), 256, PROJ_SMEM>>>(proj_b, out);
}

// round 7
// speedup vs baseline: 1.1716x; 1.1716x over previous
#include <cuda_runtime.h>
#include <cuda_bf16.h>
#include <cuda_fp16.h>
#include <math.h>
#include <stdint.h>

#define M_TOTAL 131072  // 2048 windows * 64 tokens

// ---------------- scratch (device globals) ----------------
__device__ float         g_qkv[(size_t)M_TOTAL * 768];   // fp32 qkv (qn|kn|v), q/k pre-normalized
__device__ __nv_bfloat16 g_a1[(size_t)M_TOTAL * 768];    // x split [hi|lo|hi] (bf16)
__device__ __half        g_a2[(size_t)M_TOTAL * 512];    // attn-out split [hi|lo] (fp16)
__device__ __nv_bfloat16 g_wq[768 * 768];                // qkv_w split [hi|hi|lo] (bf16)
__device__ __half        g_wp[256 * 256];                // proj_w hi (fp16)
__device__ float         g_bias16[8 * 64 * 64];          // 16*sigmoid(rpb)
__device__ float         g_qkvbias[768];                 // [q_bias | 0 | v_bias]

// ---------------- PTX helpers (baseline ISA only) ----------------
__device__ __forceinline__ uint32_t smem_u32(const void* p) {
    uint32_t a;
    asm("{ .reg .u64 t; cvta.to.shared.u64 t, %1; cvt.u32.u64 %0, t; }" : "=r"(a) : "l"(p));
    return a;
}

#define CP_ASYNC16(dst, src) \
    asm volatile("cp.async.cg.shared.global [%0], [%1], 16;" :: "r"((uint32_t)(dst)), "l"(src))
#define CP_COMMIT() asm volatile("cp.async.commit_group;" ::: "memory")
#define CP_WAIT(n)  asm volatile("cp.async.wait_group %0;" :: "n"(n) : "memory")

#define LDSM_X4(r, addr) \
    asm volatile("ldmatrix.sync.aligned.m8n8.x4.shared.b16 {%0,%1,%2,%3}, [%4];" \
                 : "=r"((r)[0]), "=r"((r)[1]), "=r"((r)[2]), "=r"((r)[3]) : "r"(addr))

#define MMA16816(c, a, b0, b1) \
    asm volatile("mma.sync.aligned.m16n8k16.row.col.f32.bf16.bf16.f32 " \
                 "{%0,%1,%2,%3}, {%4,%5,%6,%7}, {%8,%9}, {%0,%1,%2,%3};" \
                 : "+f"((c)[0]), "+f"((c)[1]), "+f"((c)[2]), "+f"((c)[3]) \
                 : "r"((a)[0]), "r"((a)[1]), "r"((a)[2]), "r"((a)[3]), "r"(b0), "r"(b1))

#define MMA16816H(c, a, b0, b1) \
    asm volatile("mma.sync.aligned.m16n8k16.row.col.f32.f16.f16.f32 " \
                 "{%0,%1,%2,%3}, {%4,%5,%6,%7}, {%8,%9}, {%0,%1,%2,%3};" \
                 : "+f"((c)[0]), "+f"((c)[1]), "+f"((c)[2]), "+f"((c)[3]) \
                 : "r"((a)[0]), "r"((a)[1]), "r"((a)[2]), "r"((a)[3]), "r"(b0), "r"(b1))

__device__ __forceinline__ void split2(float v, unsigned short& h, unsigned short& l) {
    __nv_bfloat16 hb = __float2bfloat16_rn(v);
    float r = v - __bfloat162float(hb);
    __nv_bfloat16 lb = __float2bfloat16_rn(r);
    h = *(unsigned short*)&hb;
    l = *(unsigned short*)&lb;
}
__device__ __forceinline__ void split2h(float v, unsigned short& h, unsigned short& l) {
    __half hb = __float2half_rn(v);
    float r = v - __half2float(hb);
    __half lb = __float2half_rn(r);
    h = *(unsigned short*)&hb;
    l = *(unsigned short*)&lb;
}
__device__ __forceinline__ unsigned short h_of(float v) {
    __half hb = __float2half_rn(v);
    return *(unsigned short*)&hb;
}

// ---------------- prep: CPB MLP bias + qkv bias vector ----------------
__global__ void prep_kernel(const float* __restrict__ cpb_w1,
                            const float* __restrict__ cpb_b1,
                            const float* __restrict__ cpb_w2,
                            const float* __restrict__ q_bias,
                            const float* __restrict__ v_bias) {
    __shared__ float bt[225][8];
    const int t = threadIdx.x;
    for (int i = t; i < 768; i += 256)
        g_qkvbias[i] = (i < 256) ? q_bias[i] : ((i < 512) ? 0.0f : v_bias[i - 512]);
    if (t < 225) {
        int i = t / 15, j = t % 15;
        float t0 = (float)(i - 7) * (8.0f / 7.0f);
        float t1 = (float)(j - 7) * (8.0f / 7.0f);
        t0 = copysignf(log2f(fabsf(t0) + 1.0f), t0) * (1.0f / 3.0f);
        t1 = copysignf(log2f(fabsf(t1) + 1.0f), t1) * (1.0f / 3.0f);
        float acc[8];
#pragma unroll
        for (int hh = 0; hh < 8; hh++) acc[hh] = 0.0f;
        for (int u = 0; u < 512; u++) {
            float hu = fmaxf(cpb_w1[2 * u] * t0 + cpb_w1[2 * u + 1] * t1 + cpb_b1[u], 0.0f);
#pragma unroll
            for (int hh = 0; hh < 8; hh++) acc[hh] += cpb_w2[hh * 512 + u] * hu;
        }
#pragma unroll
        for (int hh = 0; hh < 8; hh++) bt[t][hh] = acc[hh];
    }
    __syncthreads();
    for (int idx = t; idx < 8 * 64 * 64; idx += 256) {
        int hh = idx >> 12, n = (idx >> 6) & 63, m = idx & 63;
        int rid = ((n >> 3) - (m >> 3) + 7) * 15 + ((n & 7) - (m & 7) + 7);
        g_bias16[idx] = 16.0f / (1.0f + __expf(-bt[rid][hh]));
    }
}

// ---------------- split activations x -> g_a1 [hi|lo|hi] bf16 ----------------
__global__ __launch_bounds__(256) void split_act(const float* __restrict__ x) {
    size_t u = ((size_t)blockIdx.x * 256 + threadIdx.x) * 4;
    size_t row = u >> 8;
    int col = (int)(u & 255);
    float4 v = *(const float4*)(x + u);
    unsigned short h[4], l[4];
    split2(v.x, h[0], l[0]); split2(v.y, h[1], l[1]);
    split2(v.z, h[2], l[2]); split2(v.w, h[3], l[3]);
    uint2 hv, lv;
    hv.x = (uint32_t)h[0] | ((uint32_t)h[1] << 16);
    hv.y = (uint32_t)h[2] | ((uint32_t)h[3] << 16);
    lv.x = (uint32_t)l[0] | ((uint32_t)l[1] << 16);
    lv.y = (uint32_t)l[2] | ((uint32_t)l[3] << 16);
    __nv_bfloat16* d = g_a1 + row * 768 + col;
    *(uint2*)d = hv;
    *(uint2*)(d + 256) = lv;
    *(uint2*)(d + 512) = hv;
}

// ---------------- split qkv weights -> bf16 [hi|hi|lo] ----------------
__global__ __launch_bounds__(256) void split_wq(const float* __restrict__ w) {
    size_t u = ((size_t)blockIdx.x * 256 + threadIdx.x) * 4;
    size_t row = u >> 8;
    int col = (int)(u & 255);
    float4 v = *(const float4*)(w + u);
    unsigned short h[4], l[4];
    split2(v.x, h[0], l[0]); split2(v.y, h[1], l[1]);
    split2(v.z, h[2], l[2]); split2(v.w, h[3], l[3]);
    uint2 hv, lv;
    hv.x = (uint32_t)h[0] | ((uint32_t)h[1] << 16);
    hv.y = (uint32_t)h[2] | ((uint32_t)h[3] << 16);
    lv.x = (uint32_t)l[0] | ((uint32_t)l[1] << 16);
    lv.y = (uint32_t)l[2] | ((uint32_t)l[3] << 16);
    __nv_bfloat16* d = g_wq + row * 768 + col;
    *(uint2*)d = hv;
    *(uint2*)(d + 256) = hv;
    *(uint2*)(d + 512) = lv;
}

// ---------------- proj weights -> fp16 hi ----------------
__global__ __launch_bounds__(256) void split_wp(const float* __restrict__ w) {
    size_t u = ((size_t)blockIdx.x * 256 + threadIdx.x) * 4;
    float4 v = *(const float4*)(w + u);
    uint2 hv;
    hv.x = (uint32_t)h_of(v.x) | ((uint32_t)h_of(v.y) << 16);
    hv.y = (uint32_t)h_of(v.z) | ((uint32_t)h_of(v.w) << 16);
    *(uint2*)(g_wp + u) = hv;
}

// ---------------- qkv GEMM: bf16 3-term, 3-stage cp.async, normalize epilogue ----
__global__ __launch_bounds__(256) void qkv_mma(const float* __restrict__ ls) {
    extern __shared__ __align__(128) char smem[];
    const uint32_t sbase = smem_u32(smem);
    const int t = threadIdx.x;
    const int lane = t & 31, wid = t >> 5;
    const int bn = blockIdx.x * 128;
    const size_t bm = (size_t)blockIdx.y * 128;
    const int wm = (wid >> 2) * 64;
    const int wn = (wid & 3) * 32;

    const char* Ag = (const char*)(g_a1 + bm * 768);
    const char* Wg = (const char*)(g_wq + (size_t)bn * 768);

    auto load_chunk = [&](int c, int s) {
        uint32_t ab = sbase + s * 32768;
        uint32_t bb = ab + 16384;
        const char* Ap = Ag + c * 128;
        const char* Bp = Wg + c * 128;
#pragma unroll
        for (int i = 0; i < 4; i++) {
            int u = i * 256 + t;
            int row = u >> 3, c16 = u & 7;
            uint32_t off = (uint32_t)(row * 128 + ((c16 ^ (row & 7)) << 4));
            CP_ASYNC16(ab + off, Ap + (size_t)row * 1536 + c16 * 16);
            CP_ASYNC16(bb + off, Bp + (size_t)row * 1536 + c16 * 16);
        }
    };

    float acc[4][4][4];
#pragma unroll
    for (int mi = 0; mi < 4; mi++)
#pragma unroll
        for (int ni = 0; ni < 4; ni++)
#pragma unroll
            for (int q = 0; q < 4; q++) acc[mi][ni][q] = 0.0f;

    load_chunk(0, 0); CP_COMMIT();
    load_chunk(1, 1); CP_COMMIT();

    for (int c = 0; c < 12; c++) {
        if (c < 11) CP_WAIT(1); else CP_WAIT(0);
        __syncthreads();
        if (c + 2 < 12) { load_chunk(c + 2, (c + 2) % 3); CP_COMMIT(); }

        uint32_t ab = sbase + (c % 3) * 32768;
        uint32_t bb = ab + 16384;
#pragma unroll
        for (int ks = 0; ks < 4; ks++) {
            const int kc = ks * 2;
            uint32_t a_regs[4][4];
#pragma unroll
            for (int mi = 0; mi < 4; mi++) {
                int r = wm + mi * 16 + (lane & 15);
                int kk = kc + (lane >> 4);
                LDSM_X4(a_regs[mi], ab + r * 128 + ((kk ^ (r & 7)) << 4));
            }
            uint32_t b_regs[2][4];
#pragma unroll
            for (int np = 0; np < 2; np++) {
                int r = wn + np * 16 + (lane & 15);
                int kk = kc + (lane >> 4);
                LDSM_X4(b_regs[np], bb + r * 128 + ((kk ^ (r & 7)) << 4));
            }
#pragma unroll
            for (int mi = 0; mi < 4; mi++)
#pragma unroll
                for (int ni = 0; ni < 4; ni++) {
                    uint32_t b0 = b_regs[ni >> 1][ni & 1];
                    uint32_t b1 = b_regs[ni >> 1][(ni & 1) + 2];
                    MMA16816(acc[mi][ni], a_regs[mi], b0, b1);
                }
        }
    }

    // ---- epilogue: bias, then normalize q (with logit scale) / k per row ----
    const int g = lane >> 2, tt = lane & 3;
    const int cw = bn + wn;
    const bool isq = cw < 256;
    const bool isk = (cw >= 256) && (cw < 512);
    float scale = 1.0f;
    if (isq) scale = __expf(fminf(ls[cw >> 5], 4.6051702f));

#pragma unroll
    for (int mi = 0; mi < 4; mi++) {
        float ss0 = 0.0f, ss1 = 0.0f;
#pragma unroll
        for (int ni = 0; ni < 4; ni++) {
            int col = cw + ni * 8 + tt * 2;
            float b0 = g_qkvbias[col], b1 = g_qkvbias[col + 1];
            acc[mi][ni][0] += b0; acc[mi][ni][1] += b1;
            acc[mi][ni][2] += b0; acc[mi][ni][3] += b1;
            ss0 += acc[mi][ni][0] * acc[mi][ni][0] + acc[mi][ni][1] * acc[mi][ni][1];
            ss1 += acc[mi][ni][2] * acc[mi][ni][2] + acc[mi][ni][3] * acc[mi][ni][3];
        }
        if (isq || isk) {
            ss0 += __shfl_xor_sync(0xffffffffu, ss0, 1);
            ss0 += __shfl_xor_sync(0xffffffffu, ss0, 2);
            ss1 += __shfl_xor_sync(0xffffffffu, ss1, 1);
            ss1 += __shfl_xor_sync(0xffffffffu, ss1, 2);
            float inv0 = scale / fmaxf(sqrtf(ss0), 1e-12f);
            float inv1 = scale / fmaxf(sqrtf(ss1), 1e-12f);
#pragma unroll
            for (int ni = 0; ni < 4; ni++) {
                acc[mi][ni][0] *= inv0; acc[mi][ni][1] *= inv0;
                acc[mi][ni][2] *= inv1; acc[mi][ni][3] *= inv1;
            }
        }
        size_t r0 = bm + wm + mi * 16 + g;
#pragma unroll
        for (int ni = 0; ni < 4; ni++) {
            int col = cw + ni * 8 + tt * 2;
            *(float2*)(g_qkv + r0 * 768 + col) = make_float2(acc[mi][ni][0], acc[mi][ni][1]);
            *(float2*)(g_qkv + (r0 + 8) * 768 + col) = make_float2(acc[mi][ni][2], acc[mi][ni][3]);
        }
    }
}

// ---------------- proj GEMM: fp16 2-term (A=[hi|lo], W=hi), K'=512, 3-stage ------
__global__ __launch_bounds__(256) void proj_mma(const float* __restrict__ bias,
                                                float* __restrict__ C) {
    extern __shared__ __align__(128) char smem[];
    const uint32_t sbase = smem_u32(smem);
    const int t = threadIdx.x;
    const int lane = t & 31, wid = t >> 5;
    const int bn = blockIdx.x * 128;
    const size_t bm = (size_t)blockIdx.y * 128;
    const int wm = (wid >> 2) * 64;
    const int wn = (wid & 3) * 32;

    const char* Ag = (const char*)g_a2 + bm * 1024;      // pitch 512 fp16 = 1024B
    const char* Wg = (const char*)g_wp + (size_t)bn * 512;  // pitch 256 fp16 = 512B

    auto load_chunk = [&](int c, int s) {
        uint32_t ab = sbase + s * 32768;
        uint32_t bb = ab + 16384;
        const char* Ap = Ag + c * 128;          // chunk c: cols c*64
        const char* Bp = Wg + (c & 3) * 128;    // W section repeats every 4 chunks
#pragma unroll
        for (int i = 0; i < 4; i++) {
            int u = i * 256 + t;
            int row = u >> 3, c16 = u & 7;
            uint32_t off = (uint32_t)(row * 128 + ((c16 ^ (row & 7)) << 4));
            CP_ASYNC16(ab + off, Ap + (size_t)row * 1024 + c16 * 16);
            CP_ASYNC16(bb + off, Bp + (size_t)row * 512 + c16 * 16);
        }
    };

    float acc[4][4][4];
#pragma unroll
    for (int mi = 0; mi < 4; mi++)
#pragma unroll
        for (int ni = 0; ni < 4; ni++)
#pragma unroll
            for (int q = 0; q < 4; q++) acc[mi][ni][q] = 0.0f;

    load_chunk(0, 0); CP_COMMIT();
    load_chunk(1, 1); CP_COMMIT();

    for (int c = 0; c < 8; c++) {
        if (c < 7) CP_WAIT(1); else CP_WAIT(0);
        __syncthreads();
        if (c + 2 < 8) { load_chunk(c + 2, (c + 2) % 3); CP_COMMIT(); }

        uint32_t ab = sbase + (c % 3) * 32768;
        uint32_t bb = ab + 16384;
#pragma unroll
        for (int ks = 0; ks < 4; ks++) {
            const int kc = ks * 2;
            uint32_t a_regs[4][4];
#pragma unroll
            for (int mi = 0; mi < 4; mi++) {
                int r = wm + mi * 16 + (lane & 15);
                int kk = kc + (lane >> 4);
                LDSM_X4(a_regs[mi], ab + r * 128 + ((kk ^ (r & 7)) << 4));
            }
            uint32_t b_regs[2][4];
#pragma unroll
            for (int np = 0; np < 2; np++) {
                int r = wn + np * 16 + (lane & 15);
                int kk = kc + (lane >> 4);
                LDSM_X4(b_regs[np], bb + r * 128 + ((kk ^ (r & 7)) << 4));
            }
#pragma unroll
            for (int mi = 0; mi < 4; mi++)
#pragma unroll
                for (int ni = 0; ni < 4; ni++) {
                    uint32_t b0 = b_regs[ni >> 1][ni & 1];
                    uint32_t b1 = b_regs[ni >> 1][(ni & 1) + 2];
                    MMA16816H(acc[mi][ni], a_regs[mi], b0, b1);
                }
        }
    }

    const int g = lane >> 2, tt = lane & 3;
#pragma unroll
    for (int mi = 0; mi < 4; mi++) {
        size_t r0 = bm + wm + mi * 16 + g;
#pragma unroll
        for (int ni = 0; ni < 4; ni++) {
            int col = bn + wn + ni * 8 + tt * 2;
            float bv0 = bias[col], bv1 = bias[col + 1];
            float2 v0 = make_float2(acc[mi][ni][0] + bv0, acc[mi][ni][1] + bv1);
            float2 v1 = make_float2(acc[mi][ni][2] + bv0, acc[mi][ni][3] + bv1);
            *(float2*)(C + r0 * 256 + col) = v0;
            *(float2*)(C + (r0 + 8) * 256 + col) = v1;
        }
    }
}

// ---------------- HMMA attention (q/k pre-normalized; PV fp16 2-pass) ----------
// smem: Q'[h|l|h] bf16 64x208 @0 ; K'[h|h|l] bf16 64x208 @13312 ; VtH fp16 32x144 @26624
// sO (fp32 64x36) reuses @0 after sync.
#define ATTN_SMEM 31232
__global__ __launch_bounds__(128) void attn_mma() {
    extern __shared__ __align__(128) char smem[];
    const int b = blockIdx.x, h = blockIdx.y;
    const int t = threadIdx.x;
    const int lane = t & 31, w = t >> 5;
    const uint32_t sb = smem_u32(smem);

    const float* base = g_qkv + (size_t)b * (64 * 768) + h * 32;

    // q,k: coalesced fp32 load -> bf16 split -> MMA layouts (q:[h|l|h], k:[h|h|l])
#pragma unroll
    for (int i = 0; i < 4; i++) {
        int idx = t + i * 128;
        int n = idx >> 3;
        int d4 = (idx & 7) << 2;
        const float* rb = base + n * 768 + d4;
        float4 qv = *(const float4*)(rb);
        float4 kv = *(const float4*)(rb + 256);
        unsigned short qh[4], ql[4], kh[4], kl[4];
        split2(qv.x, qh[0], ql[0]); split2(qv.y, qh[1], ql[1]);
        split2(qv.z, qh[2], ql[2]); split2(qv.w, qh[3], ql[3]);
        split2(kv.x, kh[0], kl[0]); split2(kv.y, kh[1], kl[1]);
        split2(kv.z, kh[2], kl[2]); split2(kv.w, kh[3], kl[3]);
        uint2 qhv, qlv, khv, klv;
        qhv.x = (uint32_t)qh[0] | ((uint32_t)qh[1] << 16);
        qhv.y = (uint32_t)qh[2] | ((uint32_t)qh[3] << 16);
        qlv.x = (uint32_t)ql[0] | ((uint32_t)ql[1] << 16);
        qlv.y = (uint32_t)ql[2] | ((uint32_t)ql[3] << 16);
        khv.x = (uint32_t)kh[0] | ((uint32_t)kh[1] << 16);
        khv.y = (uint32_t)kh[2] | ((uint32_t)kh[3] << 16);
        klv.x = (uint32_t)kl[0] | ((uint32_t)kl[1] << 16);
        klv.y = (uint32_t)kl[2] | ((uint32_t)kl[3] << 16);
        char* qd = smem + n * 208 + d4 * 2;
        char* kd = smem + 13312 + n * 208 + d4 * 2;
        *(uint2*)(qd) = qhv; *(uint2*)(qd + 64) = qlv; *(uint2*)(qd + 128) = qhv;
        *(uint2*)(kd) = khv; *(uint2*)(kd + 64) = khv; *(uint2*)(kd + 128) = klv;
    }

    // V: load fp32, fp16 hi only, store transposed Vt[d][m]
    {
        int m = t >> 1, dh = (t & 1) * 16;
        const float* vr = base + m * 768 + 512 + dh;
        char* vth = smem + 26624;
#pragma unroll
        for (int i = 0; i < 16; i += 4) {
            float4 v4 = *(const float4*)(vr + i);
            float vv[4] = {v4.x, v4.y, v4.z, v4.w};
#pragma unroll
            for (int q = 0; q < 4; q++) {
                int d = dh + i + q;
                *(unsigned short*)(vth + d * 144 + m * 2) = h_of(vv[q]);
            }
        }
    }
    __syncthreads();

    // ---- QK^T: S(16x64) per warp, K'=96 bf16 ----
    const int R = w * 16;
    const uint32_t qbase = sb;
    const uint32_t kbase = sb + 13312;
    float sacc[8][4];
#pragma unroll
    for (int j = 0; j < 8; j++)
#pragma unroll
        for (int q = 0; q < 4; q++) sacc[j][q] = 0.0f;

#pragma unroll
    for (int kk = 0; kk < 6; kk++) {
        uint32_t a[4];
        {
            int r = R + (lane & 15);
            int ch = 2 * kk + (lane >> 4);
            LDSM_X4(a, qbase + r * 208 + ch * 16);
        }
#pragma unroll
        for (int nt = 0; nt < 4; nt++) {
            uint32_t br[4];
            int r = nt * 16 + (lane & 15);
            int ch = 2 * kk + (lane >> 4);
            LDSM_X4(br, kbase + r * 208 + ch * 16);
            MMA16816(sacc[nt * 2 + 0], a, br[0], br[2]);
            MMA16816(sacc[nt * 2 + 1], a, br[1], br[3]);
        }
    }

    // ---- bias + softmax in C-register layout ----
    const int g = lane >> 2, tt = lane & 3;
    const float* bp = g_bias16 + ((h * 64 + R + g) * 64);
#pragma unroll
    for (int j = 0; j < 8; j++) {
        int col = j * 8 + tt * 2;
        sacc[j][0] += bp[col];
        sacc[j][1] += bp[col + 1];
        sacc[j][2] += bp[col + 512];
        sacc[j][3] += bp[col + 513];
    }
    float m0 = -1e30f, m1 = -1e30f;
#pragma unroll
    for (int j = 0; j < 8; j++) {
        m0 = fmaxf(m0, fmaxf(sacc[j][0], sacc[j][1]));
        m1 = fmaxf(m1, fmaxf(sacc[j][2], sacc[j][3]));
    }
    m0 = fmaxf(m0, __shfl_xor_sync(0xffffffffu, m0, 1));
    m0 = fmaxf(m0, __shfl_xor_sync(0xffffffffu, m0, 2));
    m1 = fmaxf(m1, __shfl_xor_sync(0xffffffffu, m1, 1));
    m1 = fmaxf(m1, __shfl_xor_sync(0xffffffffu, m1, 2));
    float s0 = 0.0f, s1 = 0.0f;
#pragma unroll
    for (int j = 0; j < 8; j++) {
        sacc[j][0] = __expf(sacc[j][0] - m0);
        sacc[j][1] = __expf(sacc[j][1] - m0);
        sacc[j][2] = __expf(sacc[j][2] - m1);
        sacc[j][3] = __expf(sacc[j][3] - m1);
        s0 += sacc[j][0] + sacc[j][1];
        s1 += sacc[j][2] + sacc[j][3];
    }
    s0 += __shfl_xor_sync(0xffffffffu, s0, 1);
    s0 += __shfl_xor_sync(0xffffffffu, s0, 2);
    s1 += __shfl_xor_sync(0xffffffffu, s1, 1);
    s1 += __shfl_xor_sync(0xffffffffu, s1, 2);
    float r0 = 1.0f / s0, r1 = 1.0f / s1;

    // ---- P hi/lo fp16 B-fragments from registers ----
    uint32_t bh[8][2], bl[8][2];
#pragma unroll
    for (int j = 0; j < 8; j++) {
        float p0 = sacc[j][0] * r0, p1 = sacc[j][1] * r0;
        float p2 = sacc[j][2] * r1, p3 = sacc[j][3] * r1;
        unsigned short h0, l0, h1, l1, h2, l2, h3, l3;
        split2h(p0, h0, l0); split2h(p1, h1, l1);
        split2h(p2, h2, l2); split2h(p3, h3, l3);
        bh[j][0] = (uint32_t)h0 | ((uint32_t)h1 << 16);
        bl[j][0] = (uint32_t)l0 | ((uint32_t)l1 << 16);
        bh[j][1] = (uint32_t)h2 | ((uint32_t)h3 << 16);
        bl[j][1] = (uint32_t)l2 | ((uint32_t)l3 << 16);
    }

    // ---- O^T = V^T P^T: 2 fp16 passes (Vh*Ph + Vh*Pl) ----
    float oacc[2][2][4];
#pragma unroll
    for (int mt = 0; mt < 2; mt++)
#pragma unroll
        for (int nt = 0; nt < 2; nt++)
#pragma unroll
            for (int q = 0; q < 4; q++) oacc[mt][nt][q] = 0.0f;

#pragma unroll
    for (int pass = 0; pass < 2; pass++) {
        const uint32_t vbase = sb + 26624;
        uint32_t (*B)[2] = (pass == 1) ? bl : bh;
#pragma unroll
        for (int mt = 0; mt < 2; mt++) {
#pragma unroll
            for (int s = 0; s < 4; s++) {
                uint32_t a[4];
                int r = mt * 16 + (lane & 15);
                int ch = 2 * s + (lane >> 4);
                LDSM_X4(a, vbase + r * 144 + ch * 16);
                MMA16816H(oacc[mt][0], a, B[2 * s][0], B[2 * s + 1][0]);
                MMA16816H(oacc[mt][1], a, B[2 * s][1], B[2 * s + 1][1]);
            }
        }
    }

    // ---- stage O (transpose back), coalesced fp16 split write [hi|lo] ----
    __syncthreads();
    float* sO = (float*)smem;
#pragma unroll
    for (int mt = 0; mt < 2; mt++)
#pragma unroll
        for (int nt = 0; nt < 2; nt++) {
            int qr = R + nt * 8 + tt * 2;
            int d = mt * 16 + g;
            sO[qr * 36 + d] = oacc[mt][nt][0];
            sO[(qr + 1) * 36 + d] = oacc[mt][nt][1];
            sO[qr * 36 + d + 8] = oacc[mt][nt][2];
            sO[(qr + 1) * 36 + d + 8] = oacc[mt][nt][3];
        }
    __syncthreads();

    {
        int qr = t >> 1, dh = (t & 1) * 16;
        const float* orow = sO + qr * 36 + dh;
        unsigned short hi[16], lo[16];
#pragma unroll
        for (int i = 0; i < 16; i++) split2h(orow[i], hi[i], lo[i]);
        __half* og = g_a2 + (size_t)(b * 64 + qr) * 512 + h * 32 + dh;
        uint4 hv0, hv1, lv0, lv1;
        hv0.x = (uint32_t)hi[0] | ((uint32_t)hi[1] << 16);
        hv0.y = (uint32_t)hi[2] | ((uint32_t)hi[3] << 16);
        hv0.z = (uint32_t)hi[4] | ((uint32_t)hi[5] << 16);
        hv0.w = (uint32_t)hi[6] | ((uint32_t)hi[7] << 16);
        hv1.x = (uint32_t)hi[8] | ((uint32_t)hi[9] << 16);
        hv1.y = (uint32_t)hi[10] | ((uint32_t)hi[11] << 16);
        hv1.z = (uint32_t)hi[12] | ((uint32_t)hi[13] << 16);
        hv1.w = (uint32_t)hi[14] | ((uint32_t)hi[15] << 16);
        lv0.x = (uint32_t)lo[0] | ((uint32_t)lo[1] << 16);
        lv0.y = (uint32_t)lo[2] | ((uint32_t)lo[3] << 16);
        lv0.z = (uint32_t)lo[4] | ((uint32_t)lo[5] << 16);
        lv0.w = (uint32_t)lo[6] | ((uint32_t)lo[7] << 16);
        lv1.x = (uint32_t)lo[8] | ((uint32_t)lo[9] << 16);
        lv1.y = (uint32_t)lo[10] | ((uint32_t)lo[11] << 16);
        lv1.z = (uint32_t)lo[12] | ((uint32_t)lo[13] << 16);
        lv1.w = (uint32_t)lo[14] | ((uint32_t)lo[15] << 16);
        *(uint4*)(og) = hv0;
        *(uint4*)(og + 8) = hv1;
        *(uint4*)(og + 256) = lv0;
        *(uint4*)(og + 264) = lv1;
    }
}

extern "C" void kernel_launch(void* const* d_in, const int* in_sizes, int n_in,
                              void* d_out, int out_size) {
    const float* x           = (const float*)d_in[0];
    const float* qkv_w       = (const float*)d_in[1];
    const float* q_bias      = (const float*)d_in[2];
    const float* v_bias      = (const float*)d_in[3];
    const float* logit_scale = (const float*)d_in[4];
    const float* cpb_w1      = (const float*)d_in[5];
    const float* cpb_b1      = (const float*)d_in[6];
    const float* cpb_w2      = (const float*)d_in[7];
    const float* proj_w      = (const float*)d_in[8];
    const float* proj_b      = (const float*)d_in[9];
    float* out = (float*)d_out;

    const int GEMM_SMEM = 3 * 32768;  // 96 KB
    cudaFuncSetAttribute(qkv_mma, cudaFuncAttributeMaxDynamicSharedMemorySize, GEMM_SMEM);
    cudaFuncSetAttribute(proj_mma, cudaFuncAttributeMaxDynamicSharedMemorySize, GEMM_SMEM);
    cudaFuncSetAttribute(attn_mma, cudaFuncAttributeMaxDynamicSharedMemorySize, ATTN_SMEM);

    prep_kernel<<<1, 256>>>(cpb_w1, cpb_b1, cpb_w2, q_bias, v_bias);
    split_act<<<M_TOTAL * 256 / 4 / 256, 256>>>(x);
    split_wq<<<768 * 256 / 4 / 256, 256>>>(qkv_w);
    split_wp<<<256 * 256 / 4 / 256, 256>>>(proj_w);
    qkv_mma<<<dim3(6, M_TOTAL / 128), 256, GEMM_SMEM>>>(logit_scale);
    attn_mma<<<dim3(2048, 8), 128, ATTN_SMEM>>>();
    proj_mma<<<dim3(2, M_TOTAL / 128), 256, GEMM_SMEM>>>(proj_b, out);
}

// round 8
// speedup vs baseline: 1.2503x; 1.0671x over previous
#include <cuda_runtime.h>
#include <cuda_bf16.h>
#include <cuda_fp16.h>
#include <math.h>
#include <stdint.h>

#define M_TOTAL 131072  // 2048 windows * 64 tokens

// ---------------- scratch (device globals) ----------------
__device__ float         g_qkv[(size_t)M_TOTAL * 512];   // fp32 (qn|kn), pre-normalized
__device__ __half        g_v[(size_t)M_TOTAL * 256];     // v fp16-hi
__device__ __nv_bfloat16 g_a1[(size_t)M_TOTAL * 768];    // x split [hi|lo|hi] (bf16)
__device__ __half        g_a2[(size_t)M_TOTAL * 512];    // attn-out split [hi|lo] (fp16)
__device__ __nv_bfloat16 g_wq[768 * 768];                // qkv_w split [hi|hi|lo] (bf16)
__device__ __half        g_wp[256 * 256];                // proj_w hi (fp16)
__device__ float         g_bias16[8 * 64 * 64];          // 16*sigmoid(rpb)
__device__ float         g_qkvbias[768];                 // [q_bias | 0 | v_bias]

// ---------------- PTX helpers (baseline ISA only) ----------------
__device__ __forceinline__ uint32_t smem_u32(const void* p) {
    uint32_t a;
    asm("{ .reg .u64 t; cvta.to.shared.u64 t, %1; cvt.u32.u64 %0, t; }" : "=r"(a) : "l"(p));
    return a;
}

#define CP_ASYNC16(dst, src) \
    asm volatile("cp.async.cg.shared.global [%0], [%1], 16;" :: "r"((uint32_t)(dst)), "l"(src))
#define CP_COMMIT() asm volatile("cp.async.commit_group;" ::: "memory")
#define CP_WAIT(n)  asm volatile("cp.async.wait_group %0;" :: "n"(n) : "memory")

#define LDSM_X4(r, addr) \
    asm volatile("ldmatrix.sync.aligned.m8n8.x4.shared.b16 {%0,%1,%2,%3}, [%4];" \
                 : "=r"((r)[0]), "=r"((r)[1]), "=r"((r)[2]), "=r"((r)[3]) : "r"(addr))

#define MMA16816(c, a, b0, b1) \
    asm volatile("mma.sync.aligned.m16n8k16.row.col.f32.bf16.bf16.f32 " \
                 "{%0,%1,%2,%3}, {%4,%5,%6,%7}, {%8,%9}, {%0,%1,%2,%3};" \
                 : "+f"((c)[0]), "+f"((c)[1]), "+f"((c)[2]), "+f"((c)[3]) \
                 : "r"((a)[0]), "r"((a)[1]), "r"((a)[2]), "r"((a)[3]), "r"(b0), "r"(b1))

#define MMA16816H(c, a, b0, b1) \
    asm volatile("mma.sync.aligned.m16n8k16.row.col.f32.f16.f16.f32 " \
                 "{%0,%1,%2,%3}, {%4,%5,%6,%7}, {%8,%9}, {%0,%1,%2,%3};" \
                 : "+f"((c)[0]), "+f"((c)[1]), "+f"((c)[2]), "+f"((c)[3]) \
                 : "r"((a)[0]), "r"((a)[1]), "r"((a)[2]), "r"((a)[3]), "r"(b0), "r"(b1))

__device__ __forceinline__ void split2(float v, unsigned short& h, unsigned short& l) {
    __nv_bfloat16 hb = __float2bfloat16_rn(v);
    float r = v - __bfloat162float(hb);
    __nv_bfloat16 lb = __float2bfloat16_rn(r);
    h = *(unsigned short*)&hb;
    l = *(unsigned short*)&lb;
}
__device__ __forceinline__ void split2h(float v, unsigned short& h, unsigned short& l) {
    __half hb = __float2half_rn(v);
    float r = v - __half2float(hb);
    __half lb = __float2half_rn(r);
    h = *(unsigned short*)&hb;
    l = *(unsigned short*)&lb;
}
__device__ __forceinline__ unsigned short h_of(float v) {
    __half hb = __float2half_rn(v);
    return *(unsigned short*)&hb;
}

// ---------------- prep: CPB MLP bias + qkv bias vector ----------------
__global__ void prep_kernel(const float* __restrict__ cpb_w1,
                            const float* __restrict__ cpb_b1,
                            const float* __restrict__ cpb_w2,
                            const float* __restrict__ q_bias,
                            const float* __restrict__ v_bias) {
    __shared__ float bt[225][8];
    const int t = threadIdx.x;
    for (int i = t; i < 768; i += 256)
        g_qkvbias[i] = (i < 256) ? q_bias[i] : ((i < 512) ? 0.0f : v_bias[i - 512]);
    if (t < 225) {
        int i = t / 15, j = t % 15;
        float t0 = (float)(i - 7) * (8.0f / 7.0f);
        float t1 = (float)(j - 7) * (8.0f / 7.0f);
        t0 = copysignf(log2f(fabsf(t0) + 1.0f), t0) * (1.0f / 3.0f);
        t1 = copysignf(log2f(fabsf(t1) + 1.0f), t1) * (1.0f / 3.0f);
        float acc[8];
#pragma unroll
        for (int hh = 0; hh < 8; hh++) acc[hh] = 0.0f;
        for (int u = 0; u < 512; u++) {
            float hu = fmaxf(cpb_w1[2 * u] * t0 + cpb_w1[2 * u + 1] * t1 + cpb_b1[u], 0.0f);
#pragma unroll
            for (int hh = 0; hh < 8; hh++) acc[hh] += cpb_w2[hh * 512 + u] * hu;
        }
#pragma unroll
        for (int hh = 0; hh < 8; hh++) bt[t][hh] = acc[hh];
    }
    __syncthreads();
    for (int idx = t; idx < 8 * 64 * 64; idx += 256) {
        int hh = idx >> 12, n = (idx >> 6) & 63, m = idx & 63;
        int rid = ((n >> 3) - (m >> 3) + 7) * 15 + ((n & 7) - (m & 7) + 7);
        g_bias16[idx] = 16.0f / (1.0f + __expf(-bt[rid][hh]));
    }
}

// ---------------- split activations x -> g_a1 [hi|lo|hi] bf16 ----------------
__global__ __launch_bounds__(256) void split_act(const float* __restrict__ x) {
    size_t u = ((size_t)blockIdx.x * 256 + threadIdx.x) * 4;
    size_t row = u >> 8;
    int col = (int)(u & 255);
    float4 v = *(const float4*)(x + u);
    unsigned short h[4], l[4];
    split2(v.x, h[0], l[0]); split2(v.y, h[1], l[1]);
    split2(v.z, h[2], l[2]); split2(v.w, h[3], l[3]);
    uint2 hv, lv;
    hv.x = (uint32_t)h[0] | ((uint32_t)h[1] << 16);
    hv.y = (uint32_t)h[2] | ((uint32_t)h[3] << 16);
    lv.x = (uint32_t)l[0] | ((uint32_t)l[1] << 16);
    lv.y = (uint32_t)l[2] | ((uint32_t)l[3] << 16);
    __nv_bfloat16* d = g_a1 + row * 768 + col;
    *(uint2*)d = hv;
    *(uint2*)(d + 256) = lv;
    *(uint2*)(d + 512) = hv;
}

// ---------------- split qkv weights -> bf16 [hi|hi|lo] ----------------
__global__ __launch_bounds__(256) void split_wq(const float* __restrict__ w) {
    size_t u = ((size_t)blockIdx.x * 256 + threadIdx.x) * 4;
    size_t row = u >> 8;
    int col = (int)(u & 255);
    float4 v = *(const float4*)(w + u);
    unsigned short h[4], l[4];
    split2(v.x, h[0], l[0]); split2(v.y, h[1], l[1]);
    split2(v.z, h[2], l[2]); split2(v.w, h[3], l[3]);
    uint2 hv, lv;
    hv.x = (uint32_t)h[0] | ((uint32_t)h[1] << 16);
    hv.y = (uint32_t)h[2] | ((uint32_t)h[3] << 16);
    lv.x = (uint32_t)l[0] | ((uint32_t)l[1] << 16);
    lv.y = (uint32_t)l[2] | ((uint32_t)l[3] << 16);
    __nv_bfloat16* d = g_wq + row * 768 + col;
    *(uint2*)d = hv;
    *(uint2*)(d + 256) = hv;
    *(uint2*)(d + 512) = lv;
}

// ---------------- proj weights -> fp16 hi ----------------
__global__ __launch_bounds__(256) void split_wp(const float* __restrict__ w) {
    size_t u = ((size_t)blockIdx.x * 256 + threadIdx.x) * 4;
    float4 v = *(const float4*)(w + u);
    uint2 hv;
    hv.x = (uint32_t)h_of(v.x) | ((uint32_t)h_of(v.y) << 16);
    hv.y = (uint32_t)h_of(v.z) | ((uint32_t)h_of(v.w) << 16);
    *(uint2*)(g_wp + u) = hv;
}

// ---------------- qkv GEMM: bf16 3-term, 3-stage, 2 CTAs/SM ----------------
__global__ __launch_bounds__(256, 2) void qkv_mma(const float* __restrict__ ls) {
    extern __shared__ __align__(128) char smem[];
    const uint32_t sbase = smem_u32(smem);
    const int t = threadIdx.x;
    const int lane = t & 31, wid = t >> 5;
    const int bn = blockIdx.x * 128;
    const size_t bm = (size_t)blockIdx.y * 128;
    const int wm = (wid >> 2) * 64;
    const int wn = (wid & 3) * 32;

    const char* Ag = (const char*)(g_a1 + bm * 768);
    const char* Wg = (const char*)(g_wq + (size_t)bn * 768);

    auto load_chunk = [&](int c, int s) {
        uint32_t ab = sbase + s * 32768;
        uint32_t bb = ab + 16384;
        const char* Ap = Ag + c * 128;
        const char* Bp = Wg + c * 128;
#pragma unroll
        for (int i = 0; i < 4; i++) {
            int u = i * 256 + t;
            int row = u >> 3, c16 = u & 7;
            uint32_t off = (uint32_t)(row * 128 + ((c16 ^ (row & 7)) << 4));
            CP_ASYNC16(ab + off, Ap + (size_t)row * 1536 + c16 * 16);
            CP_ASYNC16(bb + off, Bp + (size_t)row * 1536 + c16 * 16);
        }
    };

    float acc[4][4][4];
#pragma unroll
    for (int mi = 0; mi < 4; mi++)
#pragma unroll
        for (int ni = 0; ni < 4; ni++)
#pragma unroll
            for (int q = 0; q < 4; q++) acc[mi][ni][q] = 0.0f;

    load_chunk(0, 0); CP_COMMIT();
    load_chunk(1, 1); CP_COMMIT();

    for (int c = 0; c < 12; c++) {
        if (c < 11) CP_WAIT(1); else CP_WAIT(0);
        __syncthreads();
        if (c + 2 < 12) { load_chunk(c + 2, (c + 2) % 3); CP_COMMIT(); }

        uint32_t ab = sbase + (c % 3) * 32768;
        uint32_t bb = ab + 16384;
#pragma unroll
        for (int ks = 0; ks < 4; ks++) {
            const int kc = ks * 2;
            uint32_t a_regs[4][4];
#pragma unroll
            for (int mi = 0; mi < 4; mi++) {
                int r = wm + mi * 16 + (lane & 15);
                int kk = kc + (lane >> 4);
                LDSM_X4(a_regs[mi], ab + r * 128 + ((kk ^ (r & 7)) << 4));
            }
            uint32_t b_regs[2][4];
#pragma unroll
            for (int np = 0; np < 2; np++) {
                int r = wn + np * 16 + (lane & 15);
                int kk = kc + (lane >> 4);
                LDSM_X4(b_regs[np], bb + r * 128 + ((kk ^ (r & 7)) << 4));
            }
#pragma unroll
            for (int mi = 0; mi < 4; mi++)
#pragma unroll
                for (int ni = 0; ni < 4; ni++) {
                    uint32_t b0 = b_regs[ni >> 1][ni & 1];
                    uint32_t b1 = b_regs[ni >> 1][(ni & 1) + 2];
                    MMA16816(acc[mi][ni], a_regs[mi], b0, b1);
                }
        }
    }

    // ---- epilogue: bias; q/k -> normalize + fp32 g_qkv (pitch 512); v -> fp16 g_v
    const int g = lane >> 2, tt = lane & 3;
    const int cw = bn + wn;
    const bool isq = cw < 256;
    const bool isv = cw >= 512;
    float scale = 1.0f;
    if (isq) scale = __expf(fminf(ls[cw >> 5], 4.6051702f));

#pragma unroll
    for (int mi = 0; mi < 4; mi++) {
        float ss0 = 0.0f, ss1 = 0.0f;
#pragma unroll
        for (int ni = 0; ni < 4; ni++) {
            int col = cw + ni * 8 + tt * 2;
            float b0 = g_qkvbias[col], b1 = g_qkvbias[col + 1];
            acc[mi][ni][0] += b0; acc[mi][ni][1] += b1;
            acc[mi][ni][2] += b0; acc[mi][ni][3] += b1;
            ss0 += acc[mi][ni][0] * acc[mi][ni][0] + acc[mi][ni][1] * acc[mi][ni][1];
            ss1 += acc[mi][ni][2] * acc[mi][ni][2] + acc[mi][ni][3] * acc[mi][ni][3];
        }
        size_t r0 = bm + wm + mi * 16 + g;
        if (!isv) {
            ss0 += __shfl_xor_sync(0xffffffffu, ss0, 1);
            ss0 += __shfl_xor_sync(0xffffffffu, ss0, 2);
            ss1 += __shfl_xor_sync(0xffffffffu, ss1, 1);
            ss1 += __shfl_xor_sync(0xffffffffu, ss1, 2);
            float inv0 = scale / fmaxf(sqrtf(ss0), 1e-12f);
            float inv1 = scale / fmaxf(sqrtf(ss1), 1e-12f);
#pragma unroll
            for (int ni = 0; ni < 4; ni++) {
                int col = cw + ni * 8 + tt * 2;
                float2 v0 = make_float2(acc[mi][ni][0] * inv0, acc[mi][ni][1] * inv0);
                float2 v1 = make_float2(acc[mi][ni][2] * inv1, acc[mi][ni][3] * inv1);
                *(float2*)(g_qkv + r0 * 512 + col) = v0;
                *(float2*)(g_qkv + (r0 + 8) * 512 + col) = v1;
            }
        } else {
#pragma unroll
            for (int ni = 0; ni < 4; ni++) {
                int vcol = (cw - 512) + ni * 8 + tt * 2;
                uint32_t p0 = (uint32_t)h_of(acc[mi][ni][0]) | ((uint32_t)h_of(acc[mi][ni][1]) << 16);
                uint32_t p1 = (uint32_t)h_of(acc[mi][ni][2]) | ((uint32_t)h_of(acc[mi][ni][3]) << 16);
                *(uint32_t*)(g_v + r0 * 256 + vcol) = p0;
                *(uint32_t*)(g_v + (r0 + 8) * 256 + vcol) = p1;
            }
        }
    }
}

// ---------------- proj GEMM: fp16 2-term (A=[hi|lo], W=hi), K'=512, 2 CTAs/SM ----
__global__ __launch_bounds__(256, 2) void proj_mma(const float* __restrict__ bias,
                                                   float* __restrict__ C) {
    extern __shared__ __align__(128) char smem[];
    const uint32_t sbase = smem_u32(smem);
    const int t = threadIdx.x;
    const int lane = t & 31, wid = t >> 5;
    const int bn = blockIdx.x * 128;
    const size_t bm = (size_t)blockIdx.y * 128;
    const int wm = (wid >> 2) * 64;
    const int wn = (wid & 3) * 32;

    const char* Ag = (const char*)g_a2 + bm * 1024;         // pitch 512 fp16 = 1024B
    const char* Wg = (const char*)g_wp + (size_t)bn * 512;  // pitch 256 fp16 = 512B

    auto load_chunk = [&](int c, int s) {
        uint32_t ab = sbase + s * 32768;
        uint32_t bb = ab + 16384;
        const char* Ap = Ag + c * 128;
        const char* Bp = Wg + (c & 3) * 128;
#pragma unroll
        for (int i = 0; i < 4; i++) {
            int u = i * 256 + t;
            int row = u >> 3, c16 = u & 7;
            uint32_t off = (uint32_t)(row * 128 + ((c16 ^ (row & 7)) << 4));
            CP_ASYNC16(ab + off, Ap + (size_t)row * 1024 + c16 * 16);
            CP_ASYNC16(bb + off, Bp + (size_t)row * 512 + c16 * 16);
        }
    };

    float acc[4][4][4];
#pragma unroll
    for (int mi = 0; mi < 4; mi++)
#pragma unroll
        for (int ni = 0; ni < 4; ni++)
#pragma unroll
            for (int q = 0; q < 4; q++) acc[mi][ni][q] = 0.0f;

    load_chunk(0, 0); CP_COMMIT();
    load_chunk(1, 1); CP_COMMIT();

    for (int c = 0; c < 8; c++) {
        if (c < 7) CP_WAIT(1); else CP_WAIT(0);
        __syncthreads();
        if (c + 2 < 8) { load_chunk(c + 2, (c + 2) % 3); CP_COMMIT(); }

        uint32_t ab = sbase + (c % 3) * 32768;
        uint32_t bb = ab + 16384;
#pragma unroll
        for (int ks = 0; ks < 4; ks++) {
            const int kc = ks * 2;
            uint32_t a_regs[4][4];
#pragma unroll
            for (int mi = 0; mi < 4; mi++) {
                int r = wm + mi * 16 + (lane & 15);
                int kk = kc + (lane >> 4);
                LDSM_X4(a_regs[mi], ab + r * 128 + ((kk ^ (r & 7)) << 4));
            }
            uint32_t b_regs[2][4];
#pragma unroll
            for (int np = 0; np < 2; np++) {
                int r = wn + np * 16 + (lane & 15);
                int kk = kc + (lane >> 4);
                LDSM_X4(b_regs[np], bb + r * 128 + ((kk ^ (r & 7)) << 4));
            }
#pragma unroll
            for (int mi = 0; mi < 4; mi++)
#pragma unroll
                for (int ni = 0; ni < 4; ni++) {
                    uint32_t b0 = b_regs[ni >> 1][ni & 1];
                    uint32_t b1 = b_regs[ni >> 1][(ni & 1) + 2];
                    MMA16816H(acc[mi][ni], a_regs[mi], b0, b1);
                }
        }
    }

    const int g = lane >> 2, tt = lane & 3;
#pragma unroll
    for (int mi = 0; mi < 4; mi++) {
        size_t r0 = bm + wm + mi * 16 + g;
#pragma unroll
        for (int ni = 0; ni < 4; ni++) {
            int col = bn + wn + ni * 8 + tt * 2;
            float bv0 = bias[col], bv1 = bias[col + 1];
            float2 v0 = make_float2(acc[mi][ni][0] + bv0, acc[mi][ni][1] + bv1);
            float2 v1 = make_float2(acc[mi][ni][2] + bv0, acc[mi][ni][3] + bv1);
            *(float2*)(C + r0 * 256 + col) = v0;
            *(float2*)(C + (r0 + 8) * 256 + col) = v1;
        }
    }
}

// ---------------- HMMA attention (q/k pre-normalized fp32; V fp16 direct) -------
// smem: Q'[h|l|h] bf16 64x208 @0 ; K'[h|h|l] bf16 64x208 @13312 ; VtH fp16 32x144 @26624
// sO (fp32 64x36) reuses @0 after sync.
#define ATTN_SMEM 31232
__global__ __launch_bounds__(128) void attn_mma() {
    extern __shared__ __align__(128) char smem[];
    const int b = blockIdx.x, h = blockIdx.y;
    const int t = threadIdx.x;
    const int lane = t & 31, w = t >> 5;
    const uint32_t sb = smem_u32(smem);

    const float* base = g_qkv + (size_t)b * (64 * 512) + h * 32;

    // q,k: coalesced fp32 load -> bf16 split -> MMA layouts (q:[h|l|h], k:[h|h|l])
#pragma unroll
    for (int i = 0; i < 4; i++) {
        int idx = t + i * 128;
        int n = idx >> 3;
        int d4 = (idx & 7) << 2;
        const float* rb = base + n * 512 + d4;
        float4 qv = *(const float4*)(rb);
        float4 kv = *(const float4*)(rb + 256);
        unsigned short qh[4], ql[4], kh[4], kl[4];
        split2(qv.x, qh[0], ql[0]); split2(qv.y, qh[1], ql[1]);
        split2(qv.z, qh[2], ql[2]); split2(qv.w, qh[3], ql[3]);
        split2(kv.x, kh[0], kl[0]); split2(kv.y, kh[1], kl[1]);
        split2(kv.z, kh[2], kl[2]); split2(kv.w, kh[3], kl[3]);
        uint2 qhv, qlv, khv, klv;
        qhv.x = (uint32_t)qh[0] | ((uint32_t)qh[1] << 16);
        qhv.y = (uint32_t)qh[2] | ((uint32_t)qh[3] << 16);
        qlv.x = (uint32_t)ql[0] | ((uint32_t)ql[1] << 16);
        qlv.y = (uint32_t)ql[2] | ((uint32_t)ql[3] << 16);
        khv.x = (uint32_t)kh[0] | ((uint32_t)kh[1] << 16);
        khv.y = (uint32_t)kh[2] | ((uint32_t)kh[3] << 16);
        klv.x = (uint32_t)kl[0] | ((uint32_t)kl[1] << 16);
        klv.y = (uint32_t)kl[2] | ((uint32_t)kl[3] << 16);
        char* qd = smem + n * 208 + d4 * 2;
        char* kd = smem + 13312 + n * 208 + d4 * 2;
        *(uint2*)(qd) = qhv; *(uint2*)(qd + 64) = qlv; *(uint2*)(qd + 128) = qhv;
        *(uint2*)(kd) = khv; *(uint2*)(kd + 64) = khv; *(uint2*)(kd + 128) = klv;
    }

    // V: fp16 direct load, store transposed Vt[d][m]
    {
        int m = t >> 1, dh = (t & 1) * 16;
        const __half* vr = g_v + (size_t)(b * 64 + m) * 256 + h * 32 + dh;
        unsigned short vs[16];
        *(uint4*)(vs) = *(const uint4*)(vr);
        *(uint4*)(vs + 8) = *(const uint4*)(vr + 8);
        char* vth = smem + 26624;
#pragma unroll
        for (int i = 0; i < 16; i++)
            *(unsigned short*)(vth + (dh + i) * 144 + m * 2) = vs[i];
    }
    __syncthreads();

    // ---- QK^T: S(16x64) per warp, K'=96 bf16 ----
    const int R = w * 16;
    const uint32_t qbase = sb;
    const uint32_t kbase = sb + 13312;
    float sacc[8][4];
#pragma unroll
    for (int j = 0; j < 8; j++)
#pragma unroll
        for (int q = 0; q < 4; q++) sacc[j][q] = 0.0f;

#pragma unroll
    for (int kk = 0; kk < 6; kk++) {
        uint32_t a[4];
        {
            int r = R + (lane & 15);
            int ch = 2 * kk + (lane >> 4);
            LDSM_X4(a, qbase + r * 208 + ch * 16);
        }
#pragma unroll
        for (int nt = 0; nt < 4; nt++) {
            uint32_t br[4];
            int r = nt * 16 + (lane & 15);
            int ch = 2 * kk + (lane >> 4);
            LDSM_X4(br, kbase + r * 208 + ch * 16);
            MMA16816(sacc[nt * 2 + 0], a, br[0], br[2]);
            MMA16816(sacc[nt * 2 + 1], a, br[1], br[3]);
        }
    }

    // ---- bias + softmax in C-register layout ----
    const int g = lane >> 2, tt = lane & 3;
    const float* bp = g_bias16 + ((h * 64 + R + g) * 64);
#pragma unroll
    for (int j = 0; j < 8; j++) {
        int col = j * 8 + tt * 2;
        sacc[j][0] += bp[col];
        sacc[j][1] += bp[col + 1];
        sacc[j][2] += bp[col + 512];
        sacc[j][3] += bp[col + 513];
    }
    float m0 = -1e30f, m1 = -1e30f;
#pragma unroll
    for (int j = 0; j < 8; j++) {
        m0 = fmaxf(m0, fmaxf(sacc[j][0], sacc[j][1]));
        m1 = fmaxf(m1, fmaxf(sacc[j][2], sacc[j][3]));
    }
    m0 = fmaxf(m0, __shfl_xor_sync(0xffffffffu, m0, 1));
    m0 = fmaxf(m0, __shfl_xor_sync(0xffffffffu, m0, 2));
    m1 = fmaxf(m1, __shfl_xor_sync(0xffffffffu, m1, 1));
    m1 = fmaxf(m1, __shfl_xor_sync(0xffffffffu, m1, 2));
    float s0 = 0.0f, s1 = 0.0f;
#pragma unroll
    for (int j = 0; j < 8; j++) {
        sacc[j][0] = __expf(sacc[j][0] - m0);
        sacc[j][1] = __expf(sacc[j][1] - m0);
        sacc[j][2] = __expf(sacc[j][2] - m1);
        sacc[j][3] = __expf(sacc[j][3] - m1);
        s0 += sacc[j][0] + sacc[j][1];
        s1 += sacc[j][2] + sacc[j][3];
    }
    s0 += __shfl_xor_sync(0xffffffffu, s0, 1);
    s0 += __shfl_xor_sync(0xffffffffu, s0, 2);
    s1 += __shfl_xor_sync(0xffffffffu, s1, 1);
    s1 += __shfl_xor_sync(0xffffffffu, s1, 2);
    float r0 = 1.0f / s0, r1 = 1.0f / s1;

    // ---- P hi/lo fp16 B-fragments from registers ----
    uint32_t bh[8][2], bl[8][2];
#pragma unroll
    for (int j = 0; j < 8; j++) {
        float p0 = sacc[j][0] * r0, p1 = sacc[j][1] * r0;
        float p2 = sacc[j][2] * r1, p3 = sacc[j][3] * r1;
        unsigned short h0, l0, h1, l1, h2, l2, h3, l3;
        split2h(p0, h0, l0); split2h(p1, h1, l1);
        split2h(p2, h2, l2); split2h(p3, h3, l3);
        bh[j][0] = (uint32_t)h0 | ((uint32_t)h1 << 16);
        bl[j][0] = (uint32_t)l0 | ((uint32_t)l1 << 16);
        bh[j][1] = (uint32_t)h2 | ((uint32_t)h3 << 16);
        bl[j][1] = (uint32_t)l2 | ((uint32_t)l3 << 16);
    }

    // ---- O^T = V^T P^T: 2 fp16 passes (Vh*Ph + Vh*Pl) ----
    float oacc[2][2][4];
#pragma unroll
    for (int mt = 0; mt < 2; mt++)
#pragma unroll
        for (int nt = 0; nt < 2; nt++)
#pragma unroll
            for (int q = 0; q < 4; q++) oacc[mt][nt][q] = 0.0f;

#pragma unroll
    for (int pass = 0; pass < 2; pass++) {
        const uint32_t vbase = sb + 26624;
        uint32_t (*B)[2] = (pass == 1) ? bl : bh;
#pragma unroll
        for (int mt = 0; mt < 2; mt++) {
#pragma unroll
            for (int s = 0; s < 4; s++) {
                uint32_t a[4];
                int r = mt * 16 + (lane & 15);
                int ch = 2 * s + (lane >> 4);
                LDSM_X4(a, vbase + r * 144 + ch * 16);
                MMA16816H(oacc[mt][0], a, B[2 * s][0], B[2 * s + 1][0]);
                MMA16816H(oacc[mt][1], a, B[2 * s][1], B[2 * s + 1][1]);
            }
        }
    }

    // ---- stage O (transpose back), coalesced fp16 split write [hi|lo] ----
    __syncthreads();
    float* sO = (float*)smem;
#pragma unroll
    for (int mt = 0; mt < 2; mt++)
#pragma unroll
        for (int nt = 0; nt < 2; nt++) {
            int qr = R + nt * 8 + tt * 2;
            int d = mt * 16 + g;
            sO[qr * 36 + d] = oacc[mt][nt][0];
            sO[(qr + 1) * 36 + d] = oacc[mt][nt][1];
            sO[qr * 36 + d + 8] = oacc[mt][nt][2];
            sO[(qr + 1) * 36 + d + 8] = oacc[mt][nt][3];
        }
    __syncthreads();

    {
        int qr = t >> 1, dh = (t & 1) * 16;
        const float* orow = sO + qr * 36 + dh;
        unsigned short hi[16], lo[16];
#pragma unroll
        for (int i = 0; i < 16; i++) split2h(orow[i], hi[i], lo[i]);
        __half* og = g_a2 + (size_t)(b * 64 + qr) * 512 + h * 32 + dh;
        uint4 hv0, hv1, lv0, lv1;
        hv0.x = (uint32_t)hi[0] | ((uint32_t)hi[1] << 16);
        hv0.y = (uint32_t)hi[2] | ((uint32_t)hi[3] << 16);
        hv0.z = (uint32_t)hi[4] | ((uint32_t)hi[5] << 16);
        hv0.w = (uint32_t)hi[6] | ((uint32_t)hi[7] << 16);
        hv1.x = (uint32_t)hi[8] | ((uint32_t)hi[9] << 16);
        hv1.y = (uint32_t)hi[10] | ((uint32_t)hi[11] << 16);
        hv1.z = (uint32_t)hi[12] | ((uint32_t)hi[13] << 16);
        hv1.w = (uint32_t)hi[14] | ((uint32_t)hi[15] << 16);
        lv0.x = (uint32_t)lo[0] | ((uint32_t)lo[1] << 16);
        lv0.y = (uint32_t)lo[2] | ((uint32_t)lo[3] << 16);
        lv0.z = (uint32_t)lo[4] | ((uint32_t)lo[5] << 16);
        lv0.w = (uint32_t)lo[6] | ((uint32_t)lo[7] << 16);
        lv1.x = (uint32_t)lo[8] | ((uint32_t)lo[9] << 16);
        lv1.y = (uint32_t)lo[10] | ((uint32_t)lo[11] << 16);
        lv1.z = (uint32_t)lo[12] | ((uint32_t)lo[13] << 16);
        lv1.w = (uint32_t)lo[14] | ((uint32_t)lo[15] << 16);
        *(uint4*)(og) = hv0;
        *(uint4*)(og + 8) = hv1;
        *(uint4*)(og + 256) = lv0;
        *(uint4*)(og + 264) = lv1;
    }
}

extern "C" void kernel_launch(void* const* d_in, const int* in_sizes, int n_in,
                              void* d_out, int out_size) {
    const float* x           = (const float*)d_in[0];
    const float* qkv_w       = (const float*)d_in[1];
    const float* q_bias      = (const float*)d_in[2];
    const float* v_bias      = (const float*)d_in[3];
    const float* logit_scale = (const float*)d_in[4];
    const float* cpb_w1      = (const float*)d_in[5];
    const float* cpb_b1      = (const float*)d_in[6];
    const float* cpb_w2      = (const float*)d_in[7];
    const float* proj_w      = (const float*)d_in[8];
    const float* proj_b      = (const float*)d_in[9];
    float* out = (float*)d_out;

    const int GEMM_SMEM = 3 * 32768;  // 96 KB, 2 CTAs/SM
    cudaFuncSetAttribute(qkv_mma, cudaFuncAttributeMaxDynamicSharedMemorySize, GEMM_SMEM);
    cudaFuncSetAttribute(proj_mma, cudaFuncAttributeMaxDynamicSharedMemorySize, GEMM_SMEM);
    cudaFuncSetAttribute(attn_mma, cudaFuncAttributeMaxDynamicSharedMemorySize, ATTN_SMEM);

    prep_kernel<<<1, 256>>>(cpb_w1, cpb_b1, cpb_w2, q_bias, v_bias);
    split_act<<<M_TOTAL * 256 / 4 / 256, 256>>>(x);
    split_wq<<<768 * 256 / 4 / 256, 256>>>(qkv_w);
    split_wp<<<256 * 256 / 4 / 256, 256>>>(proj_w);
    qkv_mma<<<dim3(6, M_TOTAL / 128), 256, GEMM_SMEM>>>(logit_scale);
    attn_mma<<<dim3(2048, 8), 128, ATTN_SMEM>>>();
    proj_mma<<<dim3(2, M_TOTAL / 128), 256, GEMM_SMEM>>>(proj_b, out);
}

// round 9
// speedup vs baseline: 1.3628x; 1.0899x over previous
#include <cuda_runtime.h>
#include <cuda_bf16.h>
#include <cuda_fp16.h>
#include <math.h>
#include <stdint.h>

#define M_TOTAL 131072  // 2048 windows * 64 tokens

// ---------------- scratch (device globals) ----------------
__device__ float         g_qkv[(size_t)M_TOTAL * 512];   // fp32 (qn|kn), pre-normalized
__device__ __half        g_v[(size_t)M_TOTAL * 256];     // v fp16-hi
__device__ __nv_bfloat16 g_a1[(size_t)M_TOTAL * 512];    // x split [hi|lo] (bf16)
__device__ __half        g_a2[(size_t)M_TOTAL * 256];    // attn-out fp16-hi
__device__ __nv_bfloat16 g_wq[768 * 768];                // qkv_w split [hi|hi|lo] (bf16)
__device__ __half        g_wp[256 * 256];                // proj_w hi (fp16)
__device__ float         g_bias16[8 * 64 * 64];          // 16*sigmoid(rpb)
__device__ float         g_qkvbias[768];                 // [q_bias | 0 | v_bias]

// ---------------- PTX helpers (baseline ISA only) ----------------
__device__ __forceinline__ uint32_t smem_u32(const void* p) {
    uint32_t a;
    asm("{ .reg .u64 t; cvta.to.shared.u64 t, %1; cvt.u32.u64 %0, t; }" : "=r"(a) : "l"(p));
    return a;
}

#define CP_ASYNC16(dst, src) \
    asm volatile("cp.async.cg.shared.global [%0], [%1], 16;" :: "r"((uint32_t)(dst)), "l"(src))
#define CP_COMMIT() asm volatile("cp.async.commit_group;" ::: "memory")
#define CP_WAIT(n)  asm volatile("cp.async.wait_group %0;" :: "n"(n) : "memory")

#define LDSM_X4(r, addr) \
    asm volatile("ldmatrix.sync.aligned.m8n8.x4.shared.b16 {%0,%1,%2,%3}, [%4];" \
                 : "=r"((r)[0]), "=r"((r)[1]), "=r"((r)[2]), "=r"((r)[3]) : "r"(addr))

#define MMA16816(c, a, b0, b1) \
    asm volatile("mma.sync.aligned.m16n8k16.row.col.f32.bf16.bf16.f32 " \
                 "{%0,%1,%2,%3}, {%4,%5,%6,%7}, {%8,%9}, {%0,%1,%2,%3};" \
                 : "+f"((c)[0]), "+f"((c)[1]), "+f"((c)[2]), "+f"((c)[3]) \
                 : "r"((a)[0]), "r"((a)[1]), "r"((a)[2]), "r"((a)[3]), "r"(b0), "r"(b1))

#define MMA16816H(c, a, b0, b1) \
    asm volatile("mma.sync.aligned.m16n8k16.row.col.f32.f16.f16.f32 " \
                 "{%0,%1,%2,%3}, {%4,%5,%6,%7}, {%8,%9}, {%0,%1,%2,%3};" \
                 : "+f"((c)[0]), "+f"((c)[1]), "+f"((c)[2]), "+f"((c)[3]) \
                 : "r"((a)[0]), "r"((a)[1]), "r"((a)[2]), "r"((a)[3]), "r"(b0), "r"(b1))

__device__ __forceinline__ void split2(float v, unsigned short& h, unsigned short& l) {
    __nv_bfloat16 hb = __float2bfloat16_rn(v);
    float r = v - __bfloat162float(hb);
    __nv_bfloat16 lb = __float2bfloat16_rn(r);
    h = *(unsigned short*)&hb;
    l = *(unsigned short*)&lb;
}
__device__ __forceinline__ unsigned short h_of(float v) {
    __half hb = __float2half_rn(v);
    return *(unsigned short*)&hb;
}

// ---------------- prep: CPB MLP bias + qkv bias vector ----------------
__global__ void prep_kernel(const float* __restrict__ cpb_w1,
                            const float* __restrict__ cpb_b1,
                            const float* __restrict__ cpb_w2,
                            const float* __restrict__ q_bias,
                            const float* __restrict__ v_bias) {
    __shared__ float bt[225][8];
    const int t = threadIdx.x;
    for (int i = t; i < 768; i += 256)
        g_qkvbias[i] = (i < 256) ? q_bias[i] : ((i < 512) ? 0.0f : v_bias[i - 512]);
    if (t < 225) {
        int i = t / 15, j = t % 15;
        float t0 = (float)(i - 7) * (8.0f / 7.0f);
        float t1 = (float)(j - 7) * (8.0f / 7.0f);
        t0 = copysignf(log2f(fabsf(t0) + 1.0f), t0) * (1.0f / 3.0f);
        t1 = copysignf(log2f(fabsf(t1) + 1.0f), t1) * (1.0f / 3.0f);
        float acc[8];
#pragma unroll
        for (int hh = 0; hh < 8; hh++) acc[hh] = 0.0f;
        for (int u = 0; u < 512; u++) {
            float hu = fmaxf(cpb_w1[2 * u] * t0 + cpb_w1[2 * u + 1] * t1 + cpb_b1[u], 0.0f);
#pragma unroll
            for (int hh = 0; hh < 8; hh++) acc[hh] += cpb_w2[hh * 512 + u] * hu;
        }
#pragma unroll
        for (int hh = 0; hh < 8; hh++) bt[t][hh] = acc[hh];
    }
    __syncthreads();
    for (int idx = t; idx < 8 * 64 * 64; idx += 256) {
        int hh = idx >> 12, n = (idx >> 6) & 63, m = idx & 63;
        int rid = ((n >> 3) - (m >> 3) + 7) * 15 + ((n & 7) - (m & 7) + 7);
        g_bias16[idx] = 16.0f / (1.0f + __expf(-bt[rid][hh]));
    }
}

// ---------------- split activations x -> g_a1 [hi|lo] bf16 (512 cols) ---------
__global__ __launch_bounds__(256) void split_act(const float* __restrict__ x) {
    size_t u = ((size_t)blockIdx.x * 256 + threadIdx.x) * 4;
    size_t row = u >> 8;
    int col = (int)(u & 255);
    float4 v = *(const float4*)(x + u);
    unsigned short h[4], l[4];
    split2(v.x, h[0], l[0]); split2(v.y, h[1], l[1]);
    split2(v.z, h[2], l[2]); split2(v.w, h[3], l[3]);
    uint2 hv, lv;
    hv.x = (uint32_t)h[0] | ((uint32_t)h[1] << 16);
    hv.y = (uint32_t)h[2] | ((uint32_t)h[3] << 16);
    lv.x = (uint32_t)l[0] | ((uint32_t)l[1] << 16);
    lv.y = (uint32_t)l[2] | ((uint32_t)l[3] << 16);
    __nv_bfloat16* d = g_a1 + row * 512 + col;
    *(uint2*)d = hv;
    *(uint2*)(d + 256) = lv;
}

// ---------------- split qkv weights -> bf16 [hi|hi|lo] ----------------
__global__ __launch_bounds__(256) void split_wq(const float* __restrict__ w) {
    size_t u = ((size_t)blockIdx.x * 256 + threadIdx.x) * 4;
    size_t row = u >> 8;
    int col = (int)(u & 255);
    float4 v = *(const float4*)(w + u);
    unsigned short h[4], l[4];
    split2(v.x, h[0], l[0]); split2(v.y, h[1], l[1]);
    split2(v.z, h[2], l[2]); split2(v.w, h[3], l[3]);
    uint2 hv, lv;
    hv.x = (uint32_t)h[0] | ((uint32_t)h[1] << 16);
    hv.y = (uint32_t)h[2] | ((uint32_t)h[3] << 16);
    lv.x = (uint32_t)l[0] | ((uint32_t)l[1] << 16);
    lv.y = (uint32_t)l[2] | ((uint32_t)l[3] << 16);
    __nv_bfloat16* d = g_wq + row * 768 + col;
    *(uint2*)d = hv;
    *(uint2*)(d + 256) = hv;
    *(uint2*)(d + 512) = lv;
}

// ---------------- proj weights -> fp16 hi ----------------
__global__ __launch_bounds__(256) void split_wp(const float* __restrict__ w) {
    size_t u = ((size_t)blockIdx.x * 256 + threadIdx.x) * 4;
    float4 v = *(const float4*)(w + u);
    uint2 hv;
    hv.x = (uint32_t)h_of(v.x) | ((uint32_t)h_of(v.y) << 16);
    hv.y = (uint32_t)h_of(v.z) | ((uint32_t)h_of(v.w) << 16);
    *(uint2*)(g_wp + u) = hv;
}

// ---------------- qkv GEMM: bf16 3-term, A section-remapped, 2 CTAs/SM ----------
__global__ __launch_bounds__(256, 2) void qkv_mma(const float* __restrict__ ls) {
    extern __shared__ __align__(128) char smem[];
    const uint32_t sbase = smem_u32(smem);
    const int t = threadIdx.x;
    const int lane = t & 31, wid = t >> 5;
    const int bn = blockIdx.x * 128;
    const size_t bm = (size_t)blockIdx.y * 128;
    const int wm = (wid >> 2) * 64;
    const int wn = (wid & 3) * 32;

    const char* Ag = (const char*)(g_a1 + bm * 512);   // pitch 512 bf16 = 1024B
    const char* Wg = (const char*)(g_wq + (size_t)bn * 768);

    auto load_chunk = [&](int c, int s) {
        uint32_t ab = sbase + s * 32768;
        uint32_t bb = ab + 16384;
        const int sec = c >> 2;  // 0:hi 1:lo 2:hi (A sections)
        const int acol = (c & 3) * 64 + ((sec == 1) ? 256 : 0);
        const char* Ap = Ag + acol * 2;
        const char* Bp = Wg + c * 128;
#pragma unroll
        for (int i = 0; i < 4; i++) {
            int u = i * 256 + t;
            int row = u >> 3, c16 = u & 7;
            uint32_t off = (uint32_t)(row * 128 + ((c16 ^ (row & 7)) << 4));
            CP_ASYNC16(ab + off, Ap + (size_t)row * 1024 + c16 * 16);
            CP_ASYNC16(bb + off, Bp + (size_t)row * 1536 + c16 * 16);
        }
    };

    float acc[4][4][4];
#pragma unroll
    for (int mi = 0; mi < 4; mi++)
#pragma unroll
        for (int ni = 0; ni < 4; ni++)
#pragma unroll
            for (int q = 0; q < 4; q++) acc[mi][ni][q] = 0.0f;

    load_chunk(0, 0); CP_COMMIT();
    load_chunk(1, 1); CP_COMMIT();

    for (int c = 0; c < 12; c++) {
        if (c < 11) CP_WAIT(1); else CP_WAIT(0);
        __syncthreads();
        if (c + 2 < 12) { load_chunk(c + 2, (c + 2) % 3); CP_COMMIT(); }

        uint32_t ab = sbase + (c % 3) * 32768;
        uint32_t bb = ab + 16384;
#pragma unroll
        for (int ks = 0; ks < 4; ks++) {
            const int kc = ks * 2;
            uint32_t a_regs[4][4];
#pragma unroll
            for (int mi = 0; mi < 4; mi++) {
                int r = wm + mi * 16 + (lane & 15);
                int kk = kc + (lane >> 4);
                LDSM_X4(a_regs[mi], ab + r * 128 + ((kk ^ (r & 7)) << 4));
            }
            uint32_t b_regs[2][4];
#pragma unroll
            for (int np = 0; np < 2; np++) {
                int r = wn + np * 16 + (lane & 15);
                int kk = kc + (lane >> 4);
                LDSM_X4(b_regs[np], bb + r * 128 + ((kk ^ (r & 7)) << 4));
            }
#pragma unroll
            for (int mi = 0; mi < 4; mi++)
#pragma unroll
                for (int ni = 0; ni < 4; ni++) {
                    uint32_t b0 = b_regs[ni >> 1][ni & 1];
                    uint32_t b1 = b_regs[ni >> 1][(ni & 1) + 2];
                    MMA16816(acc[mi][ni], a_regs[mi], b0, b1);
                }
        }
    }

    // ---- epilogue: bias; q/k -> normalize + fp32 g_qkv (pitch 512); v -> fp16 g_v
    const int g = lane >> 2, tt = lane & 3;
    const int cw = bn + wn;
    const bool isq = cw < 256;
    const bool isv = cw >= 512;
    float scale = 1.0f;
    if (isq) scale = __expf(fminf(ls[cw >> 5], 4.6051702f));

#pragma unroll
    for (int mi = 0; mi < 4; mi++) {
        float ss0 = 0.0f, ss1 = 0.0f;
#pragma unroll
        for (int ni = 0; ni < 4; ni++) {
            int col = cw + ni * 8 + tt * 2;
            float b0 = g_qkvbias[col], b1 = g_qkvbias[col + 1];
            acc[mi][ni][0] += b0; acc[mi][ni][1] += b1;
            acc[mi][ni][2] += b0; acc[mi][ni][3] += b1;
            ss0 += acc[mi][ni][0] * acc[mi][ni][0] + acc[mi][ni][1] * acc[mi][ni][1];
            ss1 += acc[mi][ni][2] * acc[mi][ni][2] + acc[mi][ni][3] * acc[mi][ni][3];
        }
        size_t r0 = bm + wm + mi * 16 + g;
        if (!isv) {
            ss0 += __shfl_xor_sync(0xffffffffu, ss0, 1);
            ss0 += __shfl_xor_sync(0xffffffffu, ss0, 2);
            ss1 += __shfl_xor_sync(0xffffffffu, ss1, 1);
            ss1 += __shfl_xor_sync(0xffffffffu, ss1, 2);
            float inv0 = scale / fmaxf(sqrtf(ss0), 1e-12f);
            float inv1 = scale / fmaxf(sqrtf(ss1), 1e-12f);
#pragma unroll
            for (int ni = 0; ni < 4; ni++) {
                int col = cw + ni * 8 + tt * 2;
                float2 v0 = make_float2(acc[mi][ni][0] * inv0, acc[mi][ni][1] * inv0);
                float2 v1 = make_float2(acc[mi][ni][2] * inv1, acc[mi][ni][3] * inv1);
                *(float2*)(g_qkv + r0 * 512 + col) = v0;
                *(float2*)(g_qkv + (r0 + 8) * 512 + col) = v1;
            }
        } else {
#pragma unroll
            for (int ni = 0; ni < 4; ni++) {
                int vcol = (cw - 512) + ni * 8 + tt * 2;
                uint32_t p0 = (uint32_t)h_of(acc[mi][ni][0]) | ((uint32_t)h_of(acc[mi][ni][1]) << 16);
                uint32_t p1 = (uint32_t)h_of(acc[mi][ni][2]) | ((uint32_t)h_of(acc[mi][ni][3]) << 16);
                *(uint32_t*)(g_v + r0 * 256 + vcol) = p0;
                *(uint32_t*)(g_v + (r0 + 8) * 256 + vcol) = p1;
            }
        }
    }
}

// ---------------- proj GEMM: fp16 1-term (A=hi, W=hi), K'=256, 2 CTAs/SM --------
__global__ __launch_bounds__(256, 2) void proj_mma(const float* __restrict__ bias,
                                                   float* __restrict__ C) {
    extern __shared__ __align__(128) char smem[];
    const uint32_t sbase = smem_u32(smem);
    const int t = threadIdx.x;
    const int lane = t & 31, wid = t >> 5;
    const int bn = blockIdx.x * 128;
    const size_t bm = (size_t)blockIdx.y * 128;
    const int wm = (wid >> 2) * 64;
    const int wn = (wid & 3) * 32;

    const char* Ag = (const char*)g_a2 + bm * 512;          // pitch 256 fp16 = 512B
    const char* Wg = (const char*)g_wp + (size_t)bn * 512;  // pitch 256 fp16 = 512B

    auto load_chunk = [&](int c, int s) {
        uint32_t ab = sbase + s * 32768;
        uint32_t bb = ab + 16384;
        const char* Ap = Ag + c * 128;
        const char* Bp = Wg + c * 128;
#pragma unroll
        for (int i = 0; i < 4; i++) {
            int u = i * 256 + t;
            int row = u >> 3, c16 = u & 7;
            uint32_t off = (uint32_t)(row * 128 + ((c16 ^ (row & 7)) << 4));
            CP_ASYNC16(ab + off, Ap + (size_t)row * 512 + c16 * 16);
            CP_ASYNC16(bb + off, Bp + (size_t)row * 512 + c16 * 16);
        }
    };

    float acc[4][4][4];
#pragma unroll
    for (int mi = 0; mi < 4; mi++)
#pragma unroll
        for (int ni = 0; ni < 4; ni++)
#pragma unroll
            for (int q = 0; q < 4; q++) acc[mi][ni][q] = 0.0f;

    load_chunk(0, 0); CP_COMMIT();
    load_chunk(1, 1); CP_COMMIT();

    for (int c = 0; c < 4; c++) {
        if (c < 3) CP_WAIT(1); else CP_WAIT(0);
        __syncthreads();
        if (c + 2 < 4) { load_chunk(c + 2, (c + 2) % 3); CP_COMMIT(); }

        uint32_t ab = sbase + (c % 3) * 32768;
        uint32_t bb = ab + 16384;
#pragma unroll
        for (int ks = 0; ks < 4; ks++) {
            const int kc = ks * 2;
            uint32_t a_regs[4][4];
#pragma unroll
            for (int mi = 0; mi < 4; mi++) {
                int r = wm + mi * 16 + (lane & 15);
                int kk = kc + (lane >> 4);
                LDSM_X4(a_regs[mi], ab + r * 128 + ((kk ^ (r & 7)) << 4));
            }
            uint32_t b_regs[2][4];
#pragma unroll
            for (int np = 0; np < 2; np++) {
                int r = wn + np * 16 + (lane & 15);
                int kk = kc + (lane >> 4);
                LDSM_X4(b_regs[np], bb + r * 128 + ((kk ^ (r & 7)) << 4));
            }
#pragma unroll
            for (int mi = 0; mi < 4; mi++)
#pragma unroll
                for (int ni = 0; ni < 4; ni++) {
                    uint32_t b0 = b_regs[ni >> 1][ni & 1];
                    uint32_t b1 = b_regs[ni >> 1][(ni & 1) + 2];
                    MMA16816H(acc[mi][ni], a_regs[mi], b0, b1);
                }
        }
    }

    const int g = lane >> 2, tt = lane & 3;
#pragma unroll
    for (int mi = 0; mi < 4; mi++) {
        size_t r0 = bm + wm + mi * 16 + g;
#pragma unroll
        for (int ni = 0; ni < 4; ni++) {
            int col = bn + wn + ni * 8 + tt * 2;
            float bv0 = bias[col], bv1 = bias[col + 1];
            float2 v0 = make_float2(acc[mi][ni][0] + bv0, acc[mi][ni][1] + bv1);
            float2 v1 = make_float2(acc[mi][ni][2] + bv0, acc[mi][ni][3] + bv1);
            *(float2*)(C + r0 * 256 + col) = v0;
            *(float2*)(C + (r0 + 8) * 256 + col) = v1;
        }
    }
}

// ---------------- HMMA attention (P fp16-hi, 1-pass PV, hi-only output) --------
// smem: Q'[h|l|h] bf16 64x208 @0 ; K'[h|h|l] bf16 64x208 @13312 ; VtH fp16 32x144 @26624
// sO (fp32 64x36) reuses @0 after sync.
#define ATTN_SMEM 31232
__global__ __launch_bounds__(128) void attn_mma() {
    extern __shared__ __align__(128) char smem[];
    const int b = blockIdx.x, h = blockIdx.y;
    const int t = threadIdx.x;
    const int lane = t & 31, w = t >> 5;
    const uint32_t sb = smem_u32(smem);

    const float* base = g_qkv + (size_t)b * (64 * 512) + h * 32;

    // q,k: coalesced fp32 load -> bf16 split -> MMA layouts (q:[h|l|h], k:[h|h|l])
#pragma unroll
    for (int i = 0; i < 4; i++) {
        int idx = t + i * 128;
        int n = idx >> 3;
        int d4 = (idx & 7) << 2;
        const float* rb = base + n * 512 + d4;
        float4 qv = *(const float4*)(rb);
        float4 kv = *(const float4*)(rb + 256);
        unsigned short qh[4], ql[4], kh[4], kl[4];
        split2(qv.x, qh[0], ql[0]); split2(qv.y, qh[1], ql[1]);
        split2(qv.z, qh[2], ql[2]); split2(qv.w, qh[3], ql[3]);
        split2(kv.x, kh[0], kl[0]); split2(kv.y, kh[1], kl[1]);
        split2(kv.z, kh[2], kl[2]); split2(kv.w, kh[3], kl[3]);
        uint2 qhv, qlv, khv, klv;
        qhv.x = (uint32_t)qh[0] | ((uint32_t)qh[1] << 16);
        qhv.y = (uint32_t)qh[2] | ((uint32_t)qh[3] << 16);
        qlv.x = (uint32_t)ql[0] | ((uint32_t)ql[1] << 16);
        qlv.y = (uint32_t)ql[2] | ((uint32_t)ql[3] << 16);
        khv.x = (uint32_t)kh[0] | ((uint32_t)kh[1] << 16);
        khv.y = (uint32_t)kh[2] | ((uint32_t)kh[3] << 16);
        klv.x = (uint32_t)kl[0] | ((uint32_t)kl[1] << 16);
        klv.y = (uint32_t)kl[2] | ((uint32_t)kl[3] << 16);
        char* qd = smem + n * 208 + d4 * 2;
        char* kd = smem + 13312 + n * 208 + d4 * 2;
        *(uint2*)(qd) = qhv; *(uint2*)(qd + 64) = qlv; *(uint2*)(qd + 128) = qhv;
        *(uint2*)(kd) = khv; *(uint2*)(kd + 64) = khv; *(uint2*)(kd + 128) = klv;
    }

    // V: fp16 direct load, store transposed Vt[d][m]
    {
        int m = t >> 1, dh = (t & 1) * 16;
        const __half* vr = g_v + (size_t)(b * 64 + m) * 256 + h * 32 + dh;
        unsigned short vs[16];
        *(uint4*)(vs) = *(const uint4*)(vr);
        *(uint4*)(vs + 8) = *(const uint4*)(vr + 8);
        char* vth = smem + 26624;
#pragma unroll
        for (int i = 0; i < 16; i++)
            *(unsigned short*)(vth + (dh + i) * 144 + m * 2) = vs[i];
    }
    __syncthreads();

    // ---- QK^T: S(16x64) per warp, K'=96 bf16 ----
    const int R = w * 16;
    const uint32_t qbase = sb;
    const uint32_t kbase = sb + 13312;
    float sacc[8][4];
#pragma unroll
    for (int j = 0; j < 8; j++)
#pragma unroll
        for (int q = 0; q < 4; q++) sacc[j][q] = 0.0f;

#pragma unroll
    for (int kk = 0; kk < 6; kk++) {
        uint32_t a[4];
        {
            int r = R + (lane & 15);
            int ch = 2 * kk + (lane >> 4);
            LDSM_X4(a, qbase + r * 208 + ch * 16);
        }
#pragma unroll
        for (int nt = 0; nt < 4; nt++) {
            uint32_t br[4];
            int r = nt * 16 + (lane & 15);
            int ch = 2 * kk + (lane >> 4);
            LDSM_X4(br, kbase + r * 208 + ch * 16);
            MMA16816(sacc[nt * 2 + 0], a, br[0], br[2]);
            MMA16816(sacc[nt * 2 + 1], a, br[1], br[3]);
        }
    }

    // ---- bias + softmax in C-register layout ----
    const int g = lane >> 2, tt = lane & 3;
    const float* bp = g_bias16 + ((h * 64 + R + g) * 64);
#pragma unroll
    for (int j = 0; j < 8; j++) {
        int col = j * 8 + tt * 2;
        sacc[j][0] += bp[col];
        sacc[j][1] += bp[col + 1];
        sacc[j][2] += bp[col + 512];
        sacc[j][3] += bp[col + 513];
    }
    float m0 = -1e30f, m1 = -1e30f;
#pragma unroll
    for (int j = 0; j < 8; j++) {
        m0 = fmaxf(m0, fmaxf(sacc[j][0], sacc[j][1]));
        m1 = fmaxf(m1, fmaxf(sacc[j][2], sacc[j][3]));
    }
    m0 = fmaxf(m0, __shfl_xor_sync(0xffffffffu, m0, 1));
    m0 = fmaxf(m0, __shfl_xor_sync(0xffffffffu, m0, 2));
    m1 = fmaxf(m1, __shfl_xor_sync(0xffffffffu, m1, 1));
    m1 = fmaxf(m1, __shfl_xor_sync(0xffffffffu, m1, 2));
    float s0 = 0.0f, s1 = 0.0f;
#pragma unroll
    for (int j = 0; j < 8; j++) {
        sacc[j][0] = __expf(sacc[j][0] - m0);
        sacc[j][1] = __expf(sacc[j][1] - m0);
        sacc[j][2] = __expf(sacc[j][2] - m1);
        sacc[j][3] = __expf(sacc[j][3] - m1);
        s0 += sacc[j][0] + sacc[j][1];
        s1 += sacc[j][2] + sacc[j][3];
    }
    s0 += __shfl_xor_sync(0xffffffffu, s0, 1);
    s0 += __shfl_xor_sync(0xffffffffu, s0, 2);
    s1 += __shfl_xor_sync(0xffffffffu, s1, 1);
    s1 += __shfl_xor_sync(0xffffffffu, s1, 2);
    float r0 = 1.0f / s0, r1 = 1.0f / s1;

    // ---- P fp16-hi B-fragments from registers ----
    uint32_t bh[8][2];
#pragma unroll
    for (int j = 0; j < 8; j++) {
        float p0 = sacc[j][0] * r0, p1 = sacc[j][1] * r0;
        float p2 = sacc[j][2] * r1, p3 = sacc[j][3] * r1;
        bh[j][0] = (uint32_t)h_of(p0) | ((uint32_t)h_of(p1) << 16);
        bh[j][1] = (uint32_t)h_of(p2) | ((uint32_t)h_of(p3) << 16);
    }

    // ---- O^T = V^T P^T: single fp16 pass ----
    float oacc[2][2][4];
#pragma unroll
    for (int mt = 0; mt < 2; mt++)
#pragma unroll
        for (int nt = 0; nt < 2; nt++)
#pragma unroll
            for (int q = 0; q < 4; q++) oacc[mt][nt][q] = 0.0f;

    {
        const uint32_t vbase = sb + 26624;
#pragma unroll
        for (int mt = 0; mt < 2; mt++) {
#pragma unroll
            for (int s = 0; s < 4; s++) {
                uint32_t a[4];
                int r = mt * 16 + (lane & 15);
                int ch = 2 * s + (lane >> 4);
                LDSM_X4(a, vbase + r * 144 + ch * 16);
                MMA16816H(oacc[mt][0], a, bh[2 * s][0], bh[2 * s + 1][0]);
                MMA16816H(oacc[mt][1], a, bh[2 * s][1], bh[2 * s + 1][1]);
            }
        }
    }

    // ---- stage O (transpose back), coalesced fp16-hi write ----
    __syncthreads();
    float* sO = (float*)smem;
#pragma unroll
    for (int mt = 0; mt < 2; mt++)
#pragma unroll
        for (int nt = 0; nt < 2; nt++) {
            int qr = R + nt * 8 + tt * 2;
            int d = mt * 16 + g;
            sO[qr * 36 + d] = oacc[mt][nt][0];
            sO[(qr + 1) * 36 + d] = oacc[mt][nt][1];
            sO[qr * 36 + d + 8] = oacc[mt][nt][2];
            sO[(qr + 1) * 36 + d + 8] = oacc[mt][nt][3];
        }
    __syncthreads();

    {
        int qr = t >> 1, dh = (t & 1) * 16;
        const float* orow = sO + qr * 36 + dh;
        unsigned short hi[16];
#pragma unroll
        for (int i = 0; i < 16; i++) hi[i] = h_of(orow[i]);
        __half* og = g_a2 + (size_t)(b * 64 + qr) * 256 + h * 32 + dh;
        uint4 hv0, hv1;
        hv0.x = (uint32_t)hi[0] | ((uint32_t)hi[1] << 16);
        hv0.y = (uint32_t)hi[2] | ((uint32_t)hi[3] << 16);
        hv0.z = (uint32_t)hi[4] | ((uint32_t)hi[5] << 16);
        hv0.w = (uint32_t)hi[6] | ((uint32_t)hi[7] << 16);
        hv1.x = (uint32_t)hi[8] | ((uint32_t)hi[9] << 16);
        hv1.y = (uint32_t)hi[10] | ((uint32_t)hi[11] << 16);
        hv1.z = (uint32_t)hi[12] | ((uint32_t)hi[13] << 16);
        hv1.w = (uint32_t)hi[14] | ((uint32_t)hi[15] << 16);
        *(uint4*)(og) = hv0;
        *(uint4*)(og + 8) = hv1;
    }
}

extern "C" void kernel_launch(void* const* d_in, const int* in_sizes, int n_in,
                              void* d_out, int out_size) {
    const float* x           = (const float*)d_in[0];
    const float* qkv_w       = (const float*)d_in[1];
    const float* q_bias      = (const float*)d_in[2];
    const float* v_bias      = (const float*)d_in[3];
    const float* logit_scale = (const float*)d_in[4];
    const float* cpb_w1      = (const float*)d_in[5];
    const float* cpb_b1      = (const float*)d_in[6];
    const float* cpb_w2      = (const float*)d_in[7];
    const float* proj_w      = (const float*)d_in[8];
    const float* proj_b      = (const float*)d_in[9];
    float* out = (float*)d_out;

    const int GEMM_SMEM = 3 * 32768;  // 96 KB, 2 CTAs/SM
    cudaFuncSetAttribute(qkv_mma, cudaFuncAttributeMaxDynamicSharedMemorySize, GEMM_SMEM);
    cudaFuncSetAttribute(proj_mma, cudaFuncAttributeMaxDynamicSharedMemorySize, GEMM_SMEM);
    cudaFuncSetAttribute(attn_mma, cudaFuncAttributeMaxDynamicSharedMemorySize, ATTN_SMEM);

    // qkv_mma is the 4th launch: ncu samples it next round.
    prep_kernel<<<1, 256>>>(cpb_w1, cpb_b1, cpb_w2, q_bias, v_bias);
    split_act<<<M_TOTAL * 256 / 4 / 256, 256>>>(x);
    split_wq<<<768 * 256 / 4 / 256, 256>>>(qkv_w);
    qkv_mma<<<dim3(6, M_TOTAL / 128), 256, GEMM_SMEM>>>(logit_scale);
    attn_mma<<<dim3(2048, 8), 128, ATTN_SMEM>>>();
    split_wp<<<256 * 256 / 4 / 256, 256>>>(proj_w);
    proj_mma<<<dim3(2, M_TOTAL / 128), 256, GEMM_SMEM>>>(proj_b, out);
}

// round 10
// speedup vs baseline: 1.5101x; 1.1081x over previous
#include <cuda_runtime.h>
#include <cuda_bf16.h>
#include <cuda_fp16.h>
#include <math.h>
#include <stdint.h>

#define M_TOTAL 131072  // 2048 windows * 64 tokens

// ---------------- scratch (device globals) ----------------
__device__ float         g_qkv[(size_t)M_TOTAL * 512];   // fp32 (qn|kn), pre-normalized
__device__ __half        g_v[(size_t)M_TOTAL * 256];     // v fp16-hi
__device__ __nv_bfloat16 g_a1[(size_t)M_TOTAL * 512];    // x split [hi|lo] (bf16)
__device__ __half        g_xh[(size_t)M_TOTAL * 256];    // x fp16-hi (for v GEMM)
__device__ __half        g_a2[(size_t)M_TOTAL * 256];    // attn-out fp16-hi
__device__ __nv_bfloat16 g_wq[768 * 768];                // qkv_w split [hi|hi|lo] (bf16)
__device__ __half        g_wv[256 * 256];                // qkv_w v-rows fp16-hi
__device__ __half        g_wp[256 * 256];                // proj_w hi (fp16)
__device__ float         g_bias16[8 * 64 * 64];          // 16*sigmoid(rpb)
__device__ float         g_qkvbias[768];                 // [q_bias | 0 | v_bias]

// ---------------- PTX helpers (baseline ISA only) ----------------
__device__ __forceinline__ uint32_t smem_u32(const void* p) {
    uint32_t a;
    asm("{ .reg .u64 t; cvta.to.shared.u64 t, %1; cvt.u32.u64 %0, t; }" : "=r"(a) : "l"(p));
    return a;
}

#define CP_ASYNC16(dst, src) \
    asm volatile("cp.async.cg.shared.global [%0], [%1], 16;" :: "r"((uint32_t)(dst)), "l"(src))
#define CP_COMMIT() asm volatile("cp.async.commit_group;" ::: "memory")
#define CP_WAIT(n)  asm volatile("cp.async.wait_group %0;" :: "n"(n) : "memory")

#define LDSM_X4(r, addr) \
    asm volatile("ldmatrix.sync.aligned.m8n8.x4.shared.b16 {%0,%1,%2,%3}, [%4];" \
                 : "=r"((r)[0]), "=r"((r)[1]), "=r"((r)[2]), "=r"((r)[3]) : "r"(addr))

#define MMA16816(c, a, b0, b1) \
    asm volatile("mma.sync.aligned.m16n8k16.row.col.f32.bf16.bf16.f32 " \
                 "{%0,%1,%2,%3}, {%4,%5,%6,%7}, {%8,%9}, {%0,%1,%2,%3};" \
                 : "+f"((c)[0]), "+f"((c)[1]), "+f"((c)[2]), "+f"((c)[3]) \
                 : "r"((a)[0]), "r"((a)[1]), "r"((a)[2]), "r"((a)[3]), "r"(b0), "r"(b1))

#define MMA16816H(c, a, b0, b1) \
    asm volatile("mma.sync.aligned.m16n8k16.row.col.f32.f16.f16.f32 " \
                 "{%0,%1,%2,%3}, {%4,%5,%6,%7}, {%8,%9}, {%0,%1,%2,%3};" \
                 : "+f"((c)[0]), "+f"((c)[1]), "+f"((c)[2]), "+f"((c)[3]) \
                 : "r"((a)[0]), "r"((a)[1]), "r"((a)[2]), "r"((a)[3]), "r"(b0), "r"(b1))

__device__ __forceinline__ void split2(float v, unsigned short& h, unsigned short& l) {
    __nv_bfloat16 hb = __float2bfloat16_rn(v);
    float r = v - __bfloat162float(hb);
    __nv_bfloat16 lb = __float2bfloat16_rn(r);
    h = *(unsigned short*)&hb;
    l = *(unsigned short*)&lb;
}
__device__ __forceinline__ unsigned short h_of(float v) {
    __half hb = __float2half_rn(v);
    return *(unsigned short*)&hb;
}

// ---------------- prep: CPB MLP bias + qkv bias vector ----------------
__global__ void prep_kernel(const float* __restrict__ cpb_w1,
                            const float* __restrict__ cpb_b1,
                            const float* __restrict__ cpb_w2,
                            const float* __restrict__ q_bias,
                            const float* __restrict__ v_bias) {
    __shared__ float bt[225][8];
    const int t = threadIdx.x;
    for (int i = t; i < 768; i += 256)
        g_qkvbias[i] = (i < 256) ? q_bias[i] : ((i < 512) ? 0.0f : v_bias[i - 512]);
    if (t < 225) {
        int i = t / 15, j = t % 15;
        float t0 = (float)(i - 7) * (8.0f / 7.0f);
        float t1 = (float)(j - 7) * (8.0f / 7.0f);
        t0 = copysignf(log2f(fabsf(t0) + 1.0f), t0) * (1.0f / 3.0f);
        t1 = copysignf(log2f(fabsf(t1) + 1.0f), t1) * (1.0f / 3.0f);
        float acc[8];
#pragma unroll
        for (int hh = 0; hh < 8; hh++) acc[hh] = 0.0f;
        for (int u = 0; u < 512; u++) {
            float hu = fmaxf(cpb_w1[2 * u] * t0 + cpb_w1[2 * u + 1] * t1 + cpb_b1[u], 0.0f);
#pragma unroll
            for (int hh = 0; hh < 8; hh++) acc[hh] += cpb_w2[hh * 512 + u] * hu;
        }
#pragma unroll
        for (int hh = 0; hh < 8; hh++) bt[t][hh] = acc[hh];
    }
    __syncthreads();
    for (int idx = t; idx < 8 * 64 * 64; idx += 256) {
        int hh = idx >> 12, n = (idx >> 6) & 63, m = idx & 63;
        int rid = ((n >> 3) - (m >> 3) + 7) * 15 + ((n & 7) - (m & 7) + 7);
        g_bias16[idx] = 16.0f / (1.0f + __expf(-bt[rid][hh]));
    }
}

// ---------------- split activations x -> g_a1 [hi|lo] bf16 + g_xh fp16 ---------
__global__ __launch_bounds__(256) void split_act(const float* __restrict__ x) {
    size_t u = ((size_t)blockIdx.x * 256 + threadIdx.x) * 4;
    size_t row = u >> 8;
    int col = (int)(u & 255);
    float4 v = *(const float4*)(x + u);
    unsigned short h[4], l[4];
    split2(v.x, h[0], l[0]); split2(v.y, h[1], l[1]);
    split2(v.z, h[2], l[2]); split2(v.w, h[3], l[3]);
    uint2 hv, lv, fv;
    hv.x = (uint32_t)h[0] | ((uint32_t)h[1] << 16);
    hv.y = (uint32_t)h[2] | ((uint32_t)h[3] << 16);
    lv.x = (uint32_t)l[0] | ((uint32_t)l[1] << 16);
    lv.y = (uint32_t)l[2] | ((uint32_t)l[3] << 16);
    fv.x = (uint32_t)h_of(v.x) | ((uint32_t)h_of(v.y) << 16);
    fv.y = (uint32_t)h_of(v.z) | ((uint32_t)h_of(v.w) << 16);
    __nv_bfloat16* d = g_a1 + row * 512 + col;
    *(uint2*)d = hv;
    *(uint2*)(d + 256) = lv;
    *(uint2*)(g_xh + row * 256 + col) = fv;
}

// ---------------- split qkv weights -> bf16 [hi|hi|lo] + v-rows fp16 ------------
__global__ __launch_bounds__(256) void split_wq(const float* __restrict__ w) {
    size_t u = ((size_t)blockIdx.x * 256 + threadIdx.x) * 4;
    size_t row = u >> 8;
    int col = (int)(u & 255);
    float4 v = *(const float4*)(w + u);
    unsigned short h[4], l[4];
    split2(v.x, h[0], l[0]); split2(v.y, h[1], l[1]);
    split2(v.z, h[2], l[2]); split2(v.w, h[3], l[3]);
    uint2 hv, lv;
    hv.x = (uint32_t)h[0] | ((uint32_t)h[1] << 16);
    hv.y = (uint32_t)h[2] | ((uint32_t)h[3] << 16);
    lv.x = (uint32_t)l[0] | ((uint32_t)l[1] << 16);
    lv.y = (uint32_t)l[2] | ((uint32_t)l[3] << 16);
    __nv_bfloat16* d = g_wq + row * 768 + col;
    *(uint2*)d = hv;
    *(uint2*)(d + 256) = hv;
    *(uint2*)(d + 512) = lv;
    if (row >= 512) {
        uint2 fv;
        fv.x = (uint32_t)h_of(v.x) | ((uint32_t)h_of(v.y) << 16);
        fv.y = (uint32_t)h_of(v.z) | ((uint32_t)h_of(v.w) << 16);
        *(uint2*)(g_wv + (row - 512) * 256 + col) = fv;
    }
}

// ---------------- proj weights -> fp16 hi ----------------
__global__ __launch_bounds__(256) void split_wp(const float* __restrict__ w) {
    size_t u = ((size_t)blockIdx.x * 256 + threadIdx.x) * 4;
    float4 v = *(const float4*)(w + u);
    uint2 hv;
    hv.x = (uint32_t)h_of(v.x) | ((uint32_t)h_of(v.y) << 16);
    hv.y = (uint32_t)h_of(v.z) | ((uint32_t)h_of(v.w) << 16);
    *(uint2*)(g_wp + u) = hv;
}

// ---------------- q,k GEMM: bf16 3-term, N=512 (q|k), normalize epilogue --------
__global__ __launch_bounds__(256, 2) void qkv_mma(const float* __restrict__ ls) {
    extern __shared__ __align__(128) char smem[];
    const uint32_t sbase = smem_u32(smem);
    const int t = threadIdx.x;
    const int lane = t & 31, wid = t >> 5;
    const int bn = blockIdx.x * 128;      // 0..511 (q|k only)
    const size_t bm = (size_t)blockIdx.y * 128;
    const int wm = (wid >> 2) * 64;
    const int wn = (wid & 3) * 32;

    const char* Ag = (const char*)(g_a1 + bm * 512);   // pitch 512 bf16 = 1024B
    const char* Wg = (const char*)(g_wq + (size_t)bn * 768);

    auto load_chunk = [&](int c, int s) {
        uint32_t ab = sbase + s * 32768;
        uint32_t bb = ab + 16384;
        const int sec = c >> 2;  // 0:hi 1:lo 2:hi (A sections)
        const int acol = (c & 3) * 64 + ((sec == 1) ? 256 : 0);
        const char* Ap = Ag + acol * 2;
        const char* Bp = Wg + c * 128;
#pragma unroll
        for (int i = 0; i < 4; i++) {
            int u = i * 256 + t;
            int row = u >> 3, c16 = u & 7;
            uint32_t off = (uint32_t)(row * 128 + ((c16 ^ (row & 7)) << 4));
            CP_ASYNC16(ab + off, Ap + (size_t)row * 1024 + c16 * 16);
            CP_ASYNC16(bb + off, Bp + (size_t)row * 1536 + c16 * 16);
        }
    };

    float acc[4][4][4];
#pragma unroll
    for (int mi = 0; mi < 4; mi++)
#pragma unroll
        for (int ni = 0; ni < 4; ni++)
#pragma unroll
            for (int q = 0; q < 4; q++) acc[mi][ni][q] = 0.0f;

    load_chunk(0, 0); CP_COMMIT();
    load_chunk(1, 1); CP_COMMIT();

    for (int c = 0; c < 12; c++) {
        if (c < 11) CP_WAIT(1); else CP_WAIT(0);
        __syncthreads();
        if (c + 2 < 12) { load_chunk(c + 2, (c + 2) % 3); CP_COMMIT(); }

        uint32_t ab = sbase + (c % 3) * 32768;
        uint32_t bb = ab + 16384;
#pragma unroll
        for (int ks = 0; ks < 4; ks++) {
            const int kc = ks * 2;
            uint32_t a_regs[4][4];
#pragma unroll
            for (int mi = 0; mi < 4; mi++) {
                int r = wm + mi * 16 + (lane & 15);
                int kk = kc + (lane >> 4);
                LDSM_X4(a_regs[mi], ab + r * 128 + ((kk ^ (r & 7)) << 4));
            }
            uint32_t b_regs[2][4];
#pragma unroll
            for (int np = 0; np < 2; np++) {
                int r = wn + np * 16 + (lane & 15);
                int kk = kc + (lane >> 4);
                LDSM_X4(b_regs[np], bb + r * 128 + ((kk ^ (r & 7)) << 4));
            }
#pragma unroll
            for (int mi = 0; mi < 4; mi++)
#pragma unroll
                for (int ni = 0; ni < 4; ni++) {
                    uint32_t b0 = b_regs[ni >> 1][ni & 1];
                    uint32_t b1 = b_regs[ni >> 1][(ni & 1) + 2];
                    MMA16816(acc[mi][ni], a_regs[mi], b0, b1);
                }
        }
    }

    // ---- epilogue: bias + normalize (q: logit scale), write fp32 g_qkv ----
    const int g = lane >> 2, tt = lane & 3;
    const int cw = bn + wn;
    const bool isq = cw < 256;
    float scale = 1.0f;
    if (isq) scale = __expf(fminf(ls[cw >> 5], 4.6051702f));

#pragma unroll
    for (int mi = 0; mi < 4; mi++) {
        float ss0 = 0.0f, ss1 = 0.0f;
#pragma unroll
        for (int ni = 0; ni < 4; ni++) {
            int col = cw + ni * 8 + tt * 2;
            float b0 = g_qkvbias[col], b1 = g_qkvbias[col + 1];
            acc[mi][ni][0] += b0; acc[mi][ni][1] += b1;
            acc[mi][ni][2] += b0; acc[mi][ni][3] += b1;
            ss0 += acc[mi][ni][0] * acc[mi][ni][0] + acc[mi][ni][1] * acc[mi][ni][1];
            ss1 += acc[mi][ni][2] * acc[mi][ni][2] + acc[mi][ni][3] * acc[mi][ni][3];
        }
        size_t r0 = bm + wm + mi * 16 + g;
        ss0 += __shfl_xor_sync(0xffffffffu, ss0, 1);
        ss0 += __shfl_xor_sync(0xffffffffu, ss0, 2);
        ss1 += __shfl_xor_sync(0xffffffffu, ss1, 1);
        ss1 += __shfl_xor_sync(0xffffffffu, ss1, 2);
        float inv0 = scale / fmaxf(sqrtf(ss0), 1e-12f);
        float inv1 = scale / fmaxf(sqrtf(ss1), 1e-12f);
#pragma unroll
        for (int ni = 0; ni < 4; ni++) {
            int col = cw + ni * 8 + tt * 2;
            float2 v0 = make_float2(acc[mi][ni][0] * inv0, acc[mi][ni][1] * inv0);
            float2 v1 = make_float2(acc[mi][ni][2] * inv1, acc[mi][ni][3] * inv1);
            *(float2*)(g_qkv + r0 * 512 + col) = v0;
            *(float2*)(g_qkv + (r0 + 8) * 512 + col) = v1;
        }
    }
}

// ---------------- v GEMM: fp16 1-term (x-hi @ wv-hi), K'=256 -> g_v fp16 --------
__global__ __launch_bounds__(256, 2) void v_mma() {
    extern __shared__ __align__(128) char smem[];
    const uint32_t sbase = smem_u32(smem);
    const int t = threadIdx.x;
    const int lane = t & 31, wid = t >> 5;
    const int bn = blockIdx.x * 128;      // 0..255 (v cols)
    const size_t bm = (size_t)blockIdx.y * 128;
    const int wm = (wid >> 2) * 64;
    const int wn = (wid & 3) * 32;

    const char* Ag = (const char*)g_xh + bm * 512;          // pitch 256 fp16 = 512B
    const char* Wg = (const char*)g_wv + (size_t)bn * 512;  // pitch 256 fp16 = 512B

    auto load_chunk = [&](int c, int s) {
        uint32_t ab = sbase + s * 32768;
        uint32_t bb = ab + 16384;
        const char* Ap = Ag + c * 128;
        const char* Bp = Wg + c * 128;
#pragma unroll
        for (int i = 0; i < 4; i++) {
            int u = i * 256 + t;
            int row = u >> 3, c16 = u & 7;
            uint32_t off = (uint32_t)(row * 128 + ((c16 ^ (row & 7)) << 4));
            CP_ASYNC16(ab + off, Ap + (size_t)row * 512 + c16 * 16);
            CP_ASYNC16(bb + off, Bp + (size_t)row * 512 + c16 * 16);
        }
    };

    float acc[4][4][4];
#pragma unroll
    for (int mi = 0; mi < 4; mi++)
#pragma unroll
        for (int ni = 0; ni < 4; ni++)
#pragma unroll
            for (int q = 0; q < 4; q++) acc[mi][ni][q] = 0.0f;

    load_chunk(0, 0); CP_COMMIT();
    load_chunk(1, 1); CP_COMMIT();

    for (int c = 0; c < 4; c++) {
        if (c < 3) CP_WAIT(1); else CP_WAIT(0);
        __syncthreads();
        if (c + 2 < 4) { load_chunk(c + 2, (c + 2) % 3); CP_COMMIT(); }

        uint32_t ab = sbase + (c % 3) * 32768;
        uint32_t bb = ab + 16384;
#pragma unroll
        for (int ks = 0; ks < 4; ks++) {
            const int kc = ks * 2;
            uint32_t a_regs[4][4];
#pragma unroll
            for (int mi = 0; mi < 4; mi++) {
                int r = wm + mi * 16 + (lane & 15);
                int kk = kc + (lane >> 4);
                LDSM_X4(a_regs[mi], ab + r * 128 + ((kk ^ (r & 7)) << 4));
            }
            uint32_t b_regs[2][4];
#pragma unroll
            for (int np = 0; np < 2; np++) {
                int r = wn + np * 16 + (lane & 15);
                int kk = kc + (lane >> 4);
                LDSM_X4(b_regs[np], bb + r * 128 + ((kk ^ (r & 7)) << 4));
            }
#pragma unroll
            for (int mi = 0; mi < 4; mi++)
#pragma unroll
                for (int ni = 0; ni < 4; ni++) {
                    uint32_t b0 = b_regs[ni >> 1][ni & 1];
                    uint32_t b1 = b_regs[ni >> 1][(ni & 1) + 2];
                    MMA16816H(acc[mi][ni], a_regs[mi], b0, b1);
                }
        }
    }

    const int g = lane >> 2, tt = lane & 3;
#pragma unroll
    for (int mi = 0; mi < 4; mi++) {
        size_t r0 = bm + wm + mi * 16 + g;
#pragma unroll
        for (int ni = 0; ni < 4; ni++) {
            int col = bn + wn + ni * 8 + tt * 2;
            float b0 = g_qkvbias[512 + col], b1 = g_qkvbias[513 + col];
            uint32_t p0 = (uint32_t)h_of(acc[mi][ni][0] + b0) | ((uint32_t)h_of(acc[mi][ni][1] + b1) << 16);
            uint32_t p1 = (uint32_t)h_of(acc[mi][ni][2] + b0) | ((uint32_t)h_of(acc[mi][ni][3] + b1) << 16);
            *(uint32_t*)(g_v + r0 * 256 + col) = p0;
            *(uint32_t*)(g_v + (r0 + 8) * 256 + col) = p1;
        }
    }
}

// ---------------- proj GEMM: fp16 1-term (A=hi, W=hi), K'=256, 2 CTAs/SM --------
__global__ __launch_bounds__(256, 2) void proj_mma(const float* __restrict__ bias,
                                                   float* __restrict__ C) {
    extern __shared__ __align__(128) char smem[];
    const uint32_t sbase = smem_u32(smem);
    const int t = threadIdx.x;
    const int lane = t & 31, wid = t >> 5;
    const int bn = blockIdx.x * 128;
    const size_t bm = (size_t)blockIdx.y * 128;
    const int wm = (wid >> 2) * 64;
    const int wn = (wid & 3) * 32;

    const char* Ag = (const char*)g_a2 + bm * 512;          // pitch 256 fp16 = 512B
    const char* Wg = (const char*)g_wp + (size_t)bn * 512;  // pitch 256 fp16 = 512B

    auto load_chunk = [&](int c, int s) {
        uint32_t ab = sbase + s * 32768;
        uint32_t bb = ab + 16384;
        const char* Ap = Ag + c * 128;
        const char* Bp = Wg + c * 128;
#pragma unroll
        for (int i = 0; i < 4; i++) {
            int u = i * 256 + t;
            int row = u >> 3, c16 = u & 7;
            uint32_t off = (uint32_t)(row * 128 + ((c16 ^ (row & 7)) << 4));
            CP_ASYNC16(ab + off, Ap + (size_t)row * 512 + c16 * 16);
            CP_ASYNC16(bb + off, Bp + (size_t)row * 512 + c16 * 16);
        }
    };

    float acc[4][4][4];
#pragma unroll
    for (int mi = 0; mi < 4; mi++)
#pragma unroll
        for (int ni = 0; ni < 4; ni++)
#pragma unroll
            for (int q = 0; q < 4; q++) acc[mi][ni][q] = 0.0f;

    load_chunk(0, 0); CP_COMMIT();
    load_chunk(1, 1); CP_COMMIT();

    for (int c = 0; c < 4; c++) {
        if (c < 3) CP_WAIT(1); else CP_WAIT(0);
        __syncthreads();
        if (c + 2 < 4) { load_chunk(c + 2, (c + 2) % 3); CP_COMMIT(); }

        uint32_t ab = sbase + (c % 3) * 32768;
        uint32_t bb = ab + 16384;
#pragma unroll
        for (int ks = 0; ks < 4; ks++) {
            const int kc = ks * 2;
            uint32_t a_regs[4][4];
#pragma unroll
            for (int mi = 0; mi < 4; mi++) {
                int r = wm + mi * 16 + (lane & 15);
                int kk = kc + (lane >> 4);
                LDSM_X4(a_regs[mi], ab + r * 128 + ((kk ^ (r & 7)) << 4));
            }
            uint32_t b_regs[2][4];
#pragma unroll
            for (int np = 0; np < 2; np++) {
                int r = wn + np * 16 + (lane & 15);
                int kk = kc + (lane >> 4);
                LDSM_X4(b_regs[np], bb + r * 128 + ((kk ^ (r & 7)) << 4));
            }
#pragma unroll
            for (int mi = 0; mi < 4; mi++)
#pragma unroll
                for (int ni = 0; ni < 4; ni++) {
                    uint32_t b0 = b_regs[ni >> 1][ni & 1];
                    uint32_t b1 = b_regs[ni >> 1][(ni & 1) + 2];
                    MMA16816H(acc[mi][ni], a_regs[mi], b0, b1);
                }
        }
    }

    const int g = lane >> 2, tt = lane & 3;
#pragma unroll
    for (int mi = 0; mi < 4; mi++) {
        size_t r0 = bm + wm + mi * 16 + g;
#pragma unroll
        for (int ni = 0; ni < 4; ni++) {
            int col = bn + wn + ni * 8 + tt * 2;
            float bv0 = bias[col], bv1 = bias[col + 1];
            float2 v0 = make_float2(acc[mi][ni][0] + bv0, acc[mi][ni][1] + bv1);
            float2 v1 = make_float2(acc[mi][ni][2] + bv0, acc[mi][ni][3] + bv1);
            *(float2*)(C + r0 * 256 + col) = v0;
            *(float2*)(C + (r0 + 8) * 256 + col) = v1;
        }
    }
}

// ---------------- HMMA attention (P fp16-hi, 1-pass PV, hi-only output) --------
// smem: Q'[h|l|h] bf16 64x208 @0 ; K'[h|h|l] bf16 64x208 @13312 ; VtH fp16 32x144 @26624
// sO (fp32 64x36) reuses @0 after sync.
#define ATTN_SMEM 31232
__global__ __launch_bounds__(128) void attn_mma() {
    extern __shared__ __align__(128) char smem[];
    const int b = blockIdx.x, h = blockIdx.y;
    const int t = threadIdx.x;
    const int lane = t & 31, w = t >> 5;
    const uint32_t sb = smem_u32(smem);

    const float* base = g_qkv + (size_t)b * (64 * 512) + h * 32;

    // q,k: coalesced fp32 load -> bf16 split -> MMA layouts (q:[h|l|h], k:[h|h|l])
#pragma unroll
    for (int i = 0; i < 4; i++) {
        int idx = t + i * 128;
        int n = idx >> 3;
        int d4 = (idx & 7) << 2;
        const float* rb = base + n * 512 + d4;
        float4 qv = *(const float4*)(rb);
        float4 kv = *(const float4*)(rb + 256);
        unsigned short qh[4], ql[4], kh[4], kl[4];
        split2(qv.x, qh[0], ql[0]); split2(qv.y, qh[1], ql[1]);
        split2(qv.z, qh[2], ql[2]); split2(qv.w, qh[3], ql[3]);
        split2(kv.x, kh[0], kl[0]); split2(kv.y, kh[1], kl[1]);
        split2(kv.z, kh[2], kl[2]); split2(kv.w, kh[3], kl[3]);
        uint2 qhv, qlv, khv, klv;
        qhv.x = (uint32_t)qh[0] | ((uint32_t)qh[1] << 16);
        qhv.y = (uint32_t)qh[2] | ((uint32_t)qh[3] << 16);
        qlv.x = (uint32_t)ql[0] | ((uint32_t)ql[1] << 16);
        qlv.y = (uint32_t)ql[2] | ((uint32_t)ql[3] << 16);
        khv.x = (uint32_t)kh[0] | ((uint32_t)kh[1] << 16);
        khv.y = (uint32_t)kh[2] | ((uint32_t)kh[3] << 16);
        klv.x = (uint32_t)kl[0] | ((uint32_t)kl[1] << 16);
        klv.y = (uint32_t)kl[2] | ((uint32_t)kl[3] << 16);
        char* qd = smem + n * 208 + d4 * 2;
        char* kd = smem + 13312 + n * 208 + d4 * 2;
        *(uint2*)(qd) = qhv; *(uint2*)(qd + 64) = qlv; *(uint2*)(qd + 128) = qhv;
        *(uint2*)(kd) = khv; *(uint2*)(kd + 64) = khv; *(uint2*)(kd + 128) = klv;
    }

    // V: fp16 direct load, store transposed Vt[d][m]
    {
        int m = t >> 1, dh = (t & 1) * 16;
        const __half* vr = g_v + (size_t)(b * 64 + m) * 256 + h * 32 + dh;
        unsigned short vs[16];
        *(uint4*)(vs) = *(const uint4*)(vr);
        *(uint4*)(vs + 8) = *(const uint4*)(vr + 8);
        char* vth = smem + 26624;
#pragma unroll
        for (int i = 0; i < 16; i++)
            *(unsigned short*)(vth + (dh + i) * 144 + m * 2) = vs[i];
    }
    __syncthreads();

    // ---- QK^T: S(16x64) per warp, K'=96 bf16 ----
    const int R = w * 16;
    const uint32_t qbase = sb;
    const uint32_t kbase = sb + 13312;
    float sacc[8][4];
#pragma unroll
    for (int j = 0; j < 8; j++)
#pragma unroll
        for (int q = 0; q < 4; q++) sacc[j][q] = 0.0f;

#pragma unroll
    for (int kk = 0; kk < 6; kk++) {
        uint32_t a[4];
        {
            int r = R + (lane & 15);
            int ch = 2 * kk + (lane >> 4);
            LDSM_X4(a, qbase + r * 208 + ch * 16);
        }
#pragma unroll
        for (int nt = 0; nt < 4; nt++) {
            uint32_t br[4];
            int r = nt * 16 + (lane & 15);
            int ch = 2 * kk + (lane >> 4);
            LDSM_X4(br, kbase + r * 208 + ch * 16);
            MMA16816(sacc[nt * 2 + 0], a, br[0], br[2]);
            MMA16816(sacc[nt * 2 + 1], a, br[1], br[3]);
        }
    }

    // ---- bias + softmax in C-register layout ----
    const int g = lane >> 2, tt = lane & 3;
    const float* bp = g_bias16 + ((h * 64 + R + g) * 64);
#pragma unroll
    for (int j = 0; j < 8; j++) {
        int col = j * 8 + tt * 2;
        sacc[j][0] += bp[col];
        sacc[j][1] += bp[col + 1];
        sacc[j][2] += bp[col + 512];
        sacc[j][3] += bp[col + 513];
    }
    float m0 = -1e30f, m1 = -1e30f;
#pragma unroll
    for (int j = 0; j < 8; j++) {
        m0 = fmaxf(m0, fmaxf(sacc[j][0], sacc[j][1]));
        m1 = fmaxf(m1, fmaxf(sacc[j][2], sacc[j][3]));
    }
    m0 = fmaxf(m0, __shfl_xor_sync(0xffffffffu, m0, 1));
    m0 = fmaxf(m0, __shfl_xor_sync(0xffffffffu, m0, 2));
    m1 = fmaxf(m1, __shfl_xor_sync(0xffffffffu, m1, 1));
    m1 = fmaxf(m1, __shfl_xor_sync(0xffffffffu, m1, 2));
    float s0 = 0.0f, s1 = 0.0f;
#pragma unroll
    for (int j = 0; j < 8; j++) {
        sacc[j][0] = __expf(sacc[j][0] - m0);
        sacc[j][1] = __expf(sacc[j][1] - m0);
        sacc[j][2] = __expf(sacc[j][2] - m1);
        sacc[j][3] = __expf(sacc[j][3] - m1);
        s0 += sacc[j][0] + sacc[j][1];
        s1 += sacc[j][2] + sacc[j][3];
    }
    s0 += __shfl_xor_sync(0xffffffffu, s0, 1);
    s0 += __shfl_xor_sync(0xffffffffu, s0, 2);
    s1 += __shfl_xor_sync(0xffffffffu, s1, 1);
    s1 += __shfl_xor_sync(0xffffffffu, s1, 2);
    float r0 = 1.0f / s0, r1 = 1.0f / s1;

    // ---- P fp16-hi B-fragments from registers ----
    uint32_t bh[8][2];
#pragma unroll
    for (int j = 0; j < 8; j++) {
        float p0 = sacc[j][0] * r0, p1 = sacc[j][1] * r0;
        float p2 = sacc[j][2] * r1, p3 = sacc[j][3] * r1;
        bh[j][0] = (uint32_t)h_of(p0) | ((uint32_t)h_of(p1) << 16);
        bh[j][1] = (uint32_t)h_of(p2) | ((uint32_t)h_of(p3) << 16);
    }

    // ---- O^T = V^T P^T: single fp16 pass ----
    float oacc[2][2][4];
#pragma unroll
    for (int mt = 0; mt < 2; mt++)
#pragma unroll
        for (int nt = 0; nt < 2; nt++)
#pragma unroll
            for (int q = 0; q < 4; q++) oacc[mt][nt][q] = 0.0f;

    {
        const uint32_t vbase = sb + 26624;
#pragma unroll
        for (int mt = 0; mt < 2; mt++) {
#pragma unroll
            for (int s = 0; s < 4; s++) {
                uint32_t a[4];
                int r = mt * 16 + (lane & 15);
                int ch = 2 * s + (lane >> 4);
                LDSM_X4(a, vbase + r * 144 + ch * 16);
                MMA16816H(oacc[mt][0], a, bh[2 * s][0], bh[2 * s + 1][0]);
                MMA16816H(oacc[mt][1], a, bh[2 * s][1], bh[2 * s + 1][1]);
            }
        }
    }

    // ---- stage O (transpose back), coalesced fp16-hi write ----
    __syncthreads();
    float* sO = (float*)smem;
#pragma unroll
    for (int mt = 0; mt < 2; mt++)
#pragma unroll
        for (int nt = 0; nt < 2; nt++) {
            int qr = R + nt * 8 + tt * 2;
            int d = mt * 16 + g;
            sO[qr * 36 + d] = oacc[mt][nt][0];
            sO[(qr + 1) * 36 + d] = oacc[mt][nt][1];
            sO[qr * 36 + d + 8] = oacc[mt][nt][2];
            sO[(qr + 1) * 36 + d + 8] = oacc[mt][nt][3];
        }
    __syncthreads();

    {
        int qr = t >> 1, dh = (t & 1) * 16;
        const float* orow = sO + qr * 36 + dh;
        unsigned short hi[16];
#pragma unroll
        for (int i = 0; i < 16; i++) hi[i] = h_of(orow[i]);
        __half* og = g_a2 + (size_t)(b * 64 + qr) * 256 + h * 32 + dh;
        uint4 hv0, hv1;
        hv0.x = (uint32_t)hi[0] | ((uint32_t)hi[1] << 16);
        hv0.y = (uint32_t)hi[2] | ((uint32_t)hi[3] << 16);
        hv0.z = (uint32_t)hi[4] | ((uint32_t)hi[5] << 16);
        hv0.w = (uint32_t)hi[6] | ((uint32_t)hi[7] << 16);
        hv1.x = (uint32_t)hi[8] | ((uint32_t)hi[9] << 16);
        hv1.y = (uint32_t)hi[10] | ((uint32_t)hi[11] << 16);
        hv1.z = (uint32_t)hi[12] | ((uint32_t)hi[13] << 16);
        hv1.w = (uint32_t)hi[14] | ((uint32_t)hi[15] << 16);
        *(uint4*)(og) = hv0;
        *(uint4*)(og + 8) = hv1;
    }
}

extern "C" void kernel_launch(void* const* d_in, const int* in_sizes, int n_in,
                              void* d_out, int out_size) {
    const float* x           = (const float*)d_in[0];
    const float* qkv_w       = (const float*)d_in[1];
    const float* q_bias      = (const float*)d_in[2];
    const float* v_bias      = (const float*)d_in[3];
    const float* logit_scale = (const float*)d_in[4];
    const float* cpb_w1      = (const float*)d_in[5];
    const float* cpb_b1      = (const float*)d_in[6];
    const float* cpb_w2      = (const float*)d_in[7];
    const float* proj_w      = (const float*)d_in[8];
    const float* proj_b      = (const float*)d_in[9];
    float* out = (float*)d_out;

    const int GEMM_SMEM = 3 * 32768;  // 96 KB, 2 CTAs/SM
    cudaFuncSetAttribute(qkv_mma, cudaFuncAttributeMaxDynamicSharedMemorySize, GEMM_SMEM);
    cudaFuncSetAttribute(v_mma, cudaFuncAttributeMaxDynamicSharedMemorySize, GEMM_SMEM);
    cudaFuncSetAttribute(proj_mma, cudaFuncAttributeMaxDynamicSharedMemorySize, GEMM_SMEM);
    cudaFuncSetAttribute(attn_mma, cudaFuncAttributeMaxDynamicSharedMemorySize, ATTN_SMEM);

    // qkv_mma is the 4th launch: ncu samples it.
    prep_kernel<<<1, 256>>>(cpb_w1, cpb_b1, cpb_w2, q_bias, v_bias);
    split_act<<<M_TOTAL * 256 / 4 / 256, 256>>>(x);
    split_wq<<<768 * 256 / 4 / 256, 256>>>(qkv_w);
    qkv_mma<<<dim3(4, M_TOTAL / 128), 256, GEMM_SMEM>>>(logit_scale);
    v_mma<<<dim3(2, M_TOTAL / 128), 256, GEMM_SMEM>>>();
    attn_mma<<<dim3(2048, 8), 128, ATTN_SMEM>>>();
    split_wp<<<256 * 256 / 4 / 256, 256>>>(proj_w);
    proj_mma<<<dim3(2, M_TOTAL / 128), 256, GEMM_SMEM>>>(proj_b, out);
}